// round 1
// baseline (speedup 1.0000x reference)
#include <cuda_runtime.h>
#include <math.h>

#define T 2048
#define D 512
#define H 8
#define DH 64
#define NL 2
#define FF 1024

// ---------------- scratch (static device allocations; no cudaMalloc) --------
__device__ float g_h  [T * D];
__device__ float g_ln [T * D];
__device__ float g_q  [T * D];
__device__ float g_k  [T * D];
__device__ float g_v  [T * D];
__device__ float g_att[T * D];
__device__ float g_ff [T * FF];

// ---------------- x + pos_emb ------------------------------------------------
__global__ void add_pos_kernel(const float* __restrict__ x,
                               const float* __restrict__ pos,
                               float* __restrict__ out) {
    int i = blockIdx.x * blockDim.x + threadIdx.x;   // float4 index
    float4 a = ((const float4*)x)[i];
    float4 b = ((const float4*)pos)[i];
    a.x += b.x; a.y += b.y; a.z += b.z; a.w += b.w;
    ((float4*)out)[i] = a;
}

// ---------------- LayerNorm over D=512, one block per row --------------------
__global__ void ln_kernel(const float* __restrict__ x,
                          const float* __restrict__ w,
                          const float* __restrict__ b,
                          float* __restrict__ out) {
    int row = blockIdx.x;
    int t = threadIdx.x;  // 128 threads, 4 floats each
    const float* xr = x + row * D;
    float4 v = *(const float4*)(xr + t * 4);
    float s  = v.x + v.y + v.z + v.w;
    float ss = v.x * v.x + v.y * v.y + v.z * v.z + v.w * v.w;
    #pragma unroll
    for (int o = 16; o > 0; o >>= 1) {
        s  += __shfl_xor_sync(0xffffffffu, s, o);
        ss += __shfl_xor_sync(0xffffffffu, ss, o);
    }
    __shared__ float sh[8];
    int wid = t >> 5, lane = t & 31;
    if (lane == 0) { sh[wid] = s; sh[4 + wid] = ss; }
    __syncthreads();
    float S  = sh[0] + sh[1] + sh[2] + sh[3];
    float SS = sh[4] + sh[5] + sh[6] + sh[7];
    float mu = S * (1.0f / D);
    float var = SS * (1.0f / D) - mu * mu;
    float rstd = rsqrtf(var + 1e-5f);
    float4 wv = *(const float4*)(w + t * 4);
    float4 bv = *(const float4*)(b + t * 4);
    float4 r;
    r.x = (v.x - mu) * rstd * wv.x + bv.x;
    r.y = (v.y - mu) * rstd * wv.y + bv.y;
    r.z = (v.z - mu) * rstd * wv.z + bv.z;
    r.w = (v.w - mu) * rstd * wv.w + bv.w;
    *(float4*)(out + row * D + t * 4) = r;
}

// ---------------- GEMM: C = act(A[M,K] @ W[K,N] + bias) (+ res) --------------
// 64x64 tile, BK=16, 256 threads (16x16), 4x4 microtile, transposed-A smem.
__global__ void gemm_kernel(const float* __restrict__ A,
                            const float* __restrict__ W,
                            const float* __restrict__ bias,
                            const float* __restrict__ res,
                            float* __restrict__ C,
                            int M, int N, int K, int act) {
    __shared__ float Ast[16][68];   // [k][m]
    __shared__ float Bs [16][64];   // [k][n]
    int t = threadIdx.x;
    int tx = t & 15, ty = t >> 4;
    int m0 = blockIdx.y * 64, n0 = blockIdx.x * 64;
    int arow = t >> 2, aseg = t & 3;
    int brow = t >> 4, bseg = t & 15;
    float acc[4][4] = {};
    for (int k0 = 0; k0 < K; k0 += 16) {
        float4 av = *(const float4*)(A + (size_t)(m0 + arow) * K + k0 + aseg * 4);
        float4 bv = *(const float4*)(W + (size_t)(k0 + brow) * N + n0 + bseg * 4);
        __syncthreads();
        Ast[aseg * 4 + 0][arow] = av.x;
        Ast[aseg * 4 + 1][arow] = av.y;
        Ast[aseg * 4 + 2][arow] = av.z;
        Ast[aseg * 4 + 3][arow] = av.w;
        *(float4*)&Bs[brow][bseg * 4] = bv;
        __syncthreads();
        #pragma unroll
        for (int kk = 0; kk < 16; kk++) {
            float4 a = *(const float4*)&Ast[kk][4 * ty];
            float4 b = *(const float4*)&Bs[kk][4 * tx];
            float ar[4] = {a.x, a.y, a.z, a.w};
            float br[4] = {b.x, b.y, b.z, b.w};
            #pragma unroll
            for (int i = 0; i < 4; i++)
                #pragma unroll
                for (int j = 0; j < 4; j++)
                    acc[i][j] += ar[i] * br[j];
        }
    }
    float4 bb = *(const float4*)(bias + n0 + 4 * tx);
    float bias4[4] = {bb.x, bb.y, bb.z, bb.w};
    #pragma unroll
    for (int i = 0; i < 4; i++) {
        int m = m0 + 4 * ty + i;
        float vout[4];
        #pragma unroll
        for (int j = 0; j < 4; j++) {
            float x = acc[i][j] + bias4[j];
            if (act == 1) x = 0.5f * x * (1.0f + erff(x * 0.70710678118654752f));
            vout[j] = x;
        }
        if (res) {
            float4 rv = *(const float4*)(res + (size_t)m * N + n0 + 4 * tx);
            vout[0] += rv.x; vout[1] += rv.y; vout[2] += rv.z; vout[3] += rv.w;
        }
        float4 o = {vout[0], vout[1], vout[2], vout[3]};
        *(float4*)(C + (size_t)m * N + n0 + 4 * tx) = o;
    }
}

// ---------------- Flash attention with causal band mask ----------------------
// grid (T/64, H), 256 threads. BQ=BK=64, Dh=64.
#define PADW 68
__global__ void attn_kernel(const float* __restrict__ q,
                            const float* __restrict__ k,
                            const float* __restrict__ v,
                            float* __restrict__ out, int bw) {
    extern __shared__ float sm[];
    float* Qt = sm;                 // [64][68]  (d, q)
    float* Kt = sm + 64 * PADW;     // [64][68]  (d, k)
    float* Pt = sm + 2 * 64 * PADW; // [64][68]  (k, q)
    float* Vs = sm + 3 * 64 * PADW; // [64][64]  (k, c)

    const int t = threadIdx.x;
    const int tx = t & 15, ty = t >> 4;
    const int q0 = blockIdx.x * 64;
    const int head = blockIdx.y;
    const float* qh = q + head * DH;
    const float* kh = k + head * DH;
    const float* vh = v + head * DH;

    // Load + scale Q tile (transposed)
    #pragma unroll
    for (int it = 0; it < 4; it++) {
        int e = t + it * 256;            // float4 index into 64x64 tile
        int row = e >> 4, cs = (e & 15) * 4;
        float4 qv = *(const float4*)(qh + (size_t)(q0 + row) * D + cs);
        Qt[(cs + 0) * PADW + row] = qv.x * 0.125f;
        Qt[(cs + 1) * PADW + row] = qv.y * 0.125f;
        Qt[(cs + 2) * PADW + row] = qv.z * 0.125f;
        Qt[(cs + 3) * PADW + row] = qv.w * 0.125f;
    }

    float o[4][4] = {};
    float mrow[4] = {-1e30f, -1e30f, -1e30f, -1e30f};
    float lrow[4] = {};

    int kt0 = max(0, q0 - bw) >> 6;
    int kt1 = q0 >> 6;
    for (int kt = kt0; kt <= kt1; kt++) {
        int j0 = kt << 6;
        __syncthreads();   // previous tile's P@V readers done
        #pragma unroll
        for (int it = 0; it < 4; it++) {
            int e = t + it * 256;
            int row = e >> 4, cs = (e & 15) * 4;
            float4 kv = *(const float4*)(kh + (size_t)(j0 + row) * D + cs);
            Kt[(cs + 0) * PADW + row] = kv.x;
            Kt[(cs + 1) * PADW + row] = kv.y;
            Kt[(cs + 2) * PADW + row] = kv.z;
            Kt[(cs + 3) * PADW + row] = kv.w;
            float4 vv = *(const float4*)(vh + (size_t)(j0 + row) * D + cs);
            *(float4*)&Vs[row * 64 + cs] = vv;
        }
        __syncthreads();

        // S = Q K^T (Q pre-scaled)
        float s[4][4] = {};
        #pragma unroll 8
        for (int d = 0; d < 64; d++) {
            float4 qa = *(const float4*)&Qt[d * PADW + 4 * ty];
            float4 kb = *(const float4*)&Kt[d * PADW + 4 * tx];
            float qr[4] = {qa.x, qa.y, qa.z, qa.w};
            float kr[4] = {kb.x, kb.y, kb.z, kb.w};
            #pragma unroll
            for (int i = 0; i < 4; i++)
                #pragma unroll
                for (int j = 0; j < 4; j++)
                    s[i][j] += qr[i] * kr[j];
        }
        // band mask
        #pragma unroll
        for (int i = 0; i < 4; i++) {
            int qi = q0 + 4 * ty + i;
            #pragma unroll
            for (int j = 0; j < 4; j++) {
                int kj = j0 + 4 * tx + j;
                if (kj > qi || kj < qi - bw) s[i][j] = -1e30f;
            }
        }
        // online softmax (row allreduce over tx: xor masks 1..8 stay in the
        // same 16-lane half-warp, so ty is preserved)
        #pragma unroll
        for (int i = 0; i < 4; i++) {
            float mx = fmaxf(fmaxf(s[i][0], s[i][1]), fmaxf(s[i][2], s[i][3]));
            #pragma unroll
            for (int off = 1; off < 16; off <<= 1)
                mx = fmaxf(mx, __shfl_xor_sync(0xffffffffu, mx, off));
            float mn = fmaxf(mrow[i], mx);
            float alpha = __expf(mrow[i] - mn);
            float p[4];
            float rs = 0.f;
            #pragma unroll
            for (int j = 0; j < 4; j++) {
                p[j] = (s[i][j] < -1e29f) ? 0.f : __expf(s[i][j] - mn);
                rs += p[j];
            }
            #pragma unroll
            for (int off = 1; off < 16; off <<= 1)
                rs += __shfl_xor_sync(0xffffffffu, rs, off);
            mrow[i] = mn;
            lrow[i] = lrow[i] * alpha + rs;
            #pragma unroll
            for (int j = 0; j < 4; j++) o[i][j] *= alpha;
            #pragma unroll
            for (int j = 0; j < 4; j++)
                Pt[(4 * tx + j) * PADW + 4 * ty + i] = p[j];
        }
        __syncthreads();
        // O += P V
        #pragma unroll 8
        for (int kk = 0; kk < 64; kk++) {
            float4 pa = *(const float4*)&Pt[kk * PADW + 4 * ty];
            float4 vb = *(const float4*)&Vs[kk * 64 + 4 * tx];
            float pr[4] = {pa.x, pa.y, pa.z, pa.w};
            float vr[4] = {vb.x, vb.y, vb.z, vb.w};
            #pragma unroll
            for (int i = 0; i < 4; i++)
                #pragma unroll
                for (int j = 0; j < 4; j++)
                    o[i][j] += pr[i] * vr[j];
        }
    }
    // normalize + write (row-major (T, H*Dh))
    #pragma unroll
    for (int i = 0; i < 4; i++) {
        float inv = 1.0f / lrow[i];
        float4 r = {o[i][0] * inv, o[i][1] * inv, o[i][2] * inv, o[i][3] * inv};
        *(float4*)(out + (size_t)(q0 + 4 * ty + i) * D + head * DH + 4 * tx) = r;
    }
}

// ---------------- host orchestration ----------------------------------------
extern "C" void kernel_launch(void* const* d_in, const int* in_sizes, int n_in,
                              void* d_out, int out_size) {
    const float* x      = (const float*)d_in[0];
    const float* pos    = (const float*)d_in[1];
    const float* ln1_w  = (const float*)d_in[2];
    const float* ln1_b  = (const float*)d_in[3];
    const float* ln2_w  = (const float*)d_in[4];
    const float* ln2_b  = (const float*)d_in[5];
    const float* Wq     = (const float*)d_in[6];
    const float* bq     = (const float*)d_in[7];
    const float* Wk     = (const float*)d_in[8];
    const float* bk     = (const float*)d_in[9];
    const float* Wv     = (const float*)d_in[10];
    const float* bv     = (const float*)d_in[11];
    const float* Wo     = (const float*)d_in[12];
    const float* bo     = (const float*)d_in[13];
    const float* W1     = (const float*)d_in[14];
    const float* b1     = (const float*)d_in[15];
    const float* W2     = (const float*)d_in[16];
    const float* b2     = (const float*)d_in[17];
    const float* lnf_w  = (const float*)d_in[18];
    const float* lnf_b  = (const float*)d_in[19];
    float* out = (float*)d_out;

    float *ph, *pln, *pq, *pk, *pv, *pa, *pf;
    cudaGetSymbolAddress((void**)&ph,  g_h);
    cudaGetSymbolAddress((void**)&pln, g_ln);
    cudaGetSymbolAddress((void**)&pq,  g_q);
    cudaGetSymbolAddress((void**)&pk,  g_k);
    cudaGetSymbolAddress((void**)&pv,  g_v);
    cudaGetSymbolAddress((void**)&pa,  g_att);
    cudaGetSymbolAddress((void**)&pf,  g_ff);

    const int attn_smem = (3 * 64 * PADW + 64 * 64) * (int)sizeof(float); // 68608
    cudaFuncSetAttribute(attn_kernel,
                         cudaFuncAttributeMaxDynamicSharedMemorySize, attn_smem);

    const int bands[2] = {999, 9};
    for (int s = 0; s < 2; s++) {
        add_pos_kernel<<<T * D / 4 / 256, 256>>>(x, pos, ph);
        for (int l = 0; l < NL; l++) {
            int wi = s * NL + l;
            const float* pWq = Wq + (size_t)wi * D * D;
            const float* pWk = Wk + (size_t)wi * D * D;
            const float* pWv = Wv + (size_t)wi * D * D;
            const float* pWo = Wo + (size_t)wi * D * D;
            const float* pW1 = W1 + (size_t)wi * D * FF;
            const float* pW2 = W2 + (size_t)wi * FF * D;

            ln_kernel<<<T, 128>>>(ph, ln1_w + wi * D, ln1_b + wi * D, pln);

            dim3 g8(D / 64, T / 64);
            gemm_kernel<<<g8, 256>>>(pln, pWq, bq + wi * D, nullptr, pq, T, D, D, 0);
            gemm_kernel<<<g8, 256>>>(pln, pWk, bk + wi * D, nullptr, pk, T, D, D, 0);
            gemm_kernel<<<g8, 256>>>(pln, pWv, bv + wi * D, nullptr, pv, T, D, D, 0);

            attn_kernel<<<dim3(T / 64, H), 256, attn_smem>>>(pq, pk, pv, pa, bands[s]);

            gemm_kernel<<<g8, 256>>>(pa, pWo, bo + wi * D, ph, ph, T, D, D, 0);

            ln_kernel<<<T, 128>>>(ph, ln2_w + wi * D, ln2_b + wi * D, pln);

            dim3 g16(FF / 64, T / 64);
            gemm_kernel<<<g16, 256>>>(pln, pW1, b1 + wi * FF, nullptr, pf, T, FF, D, 1);
            gemm_kernel<<<g8, 256>>>(pf, pW2, b2 + wi * D, ph, ph, T, D, FF, 0);
        }
        ln_kernel<<<T, 128>>>(ph, lnf_w, lnf_b, out + (size_t)s * T * D);
    }
}

// round 2
// speedup vs baseline: 1.2776x; 1.2776x over previous
#include <cuda_runtime.h>
#include <mma.h>
#include <math.h>

using namespace nvcuda;

#define T 2048
#define D 512
#define H 8
#define DH 64
#define NL 2
#define FF 1024

// ---------------- scratch (static device allocations; no cudaMalloc) --------
__device__ float g_h  [T * D];
__device__ float g_ln [T * D];
__device__ float g_q  [T * D];
__device__ float g_k  [T * D];
__device__ float g_v  [T * D];
__device__ float g_att[T * D];
__device__ float g_ff [T * FF];

// ---------------- x + pos_emb ------------------------------------------------
__global__ void add_pos_kernel(const float* __restrict__ x,
                               const float* __restrict__ pos,
                               float* __restrict__ out) {
    int i = blockIdx.x * blockDim.x + threadIdx.x;   // float4 index
    float4 a = ((const float4*)x)[i];
    float4 b = ((const float4*)pos)[i];
    a.x += b.x; a.y += b.y; a.z += b.z; a.w += b.w;
    ((float4*)out)[i] = a;
}

// ---------------- LayerNorm over D=512, one block per row --------------------
__global__ void ln_kernel(const float* __restrict__ x,
                          const float* __restrict__ w,
                          const float* __restrict__ b,
                          float* __restrict__ out) {
    int row = blockIdx.x;
    int t = threadIdx.x;  // 128 threads, 4 floats each
    const float* xr = x + row * D;
    float4 v = *(const float4*)(xr + t * 4);
    float s  = v.x + v.y + v.z + v.w;
    float ss = v.x * v.x + v.y * v.y + v.z * v.z + v.w * v.w;
    #pragma unroll
    for (int o = 16; o > 0; o >>= 1) {
        s  += __shfl_xor_sync(0xffffffffu, s, o);
        ss += __shfl_xor_sync(0xffffffffu, ss, o);
    }
    __shared__ float sh[8];
    int wid = t >> 5, lane = t & 31;
    if (lane == 0) { sh[wid] = s; sh[4 + wid] = ss; }
    __syncthreads();
    float S  = sh[0] + sh[1] + sh[2] + sh[3];
    float SS = sh[4] + sh[5] + sh[6] + sh[7];
    float mu = S * (1.0f / D);
    float var = SS * (1.0f / D) - mu * mu;
    float rstd = rsqrtf(var + 1e-5f);
    float4 wv = *(const float4*)(w + t * 4);
    float4 bv = *(const float4*)(b + t * 4);
    float4 r;
    r.x = (v.x - mu) * rstd * wv.x + bv.x;
    r.y = (v.y - mu) * rstd * wv.y + bv.y;
    r.z = (v.z - mu) * rstd * wv.z + bv.z;
    r.w = (v.w - mu) * rstd * wv.w + bv.w;
    *(float4*)(out + row * D + t * 4) = r;
}

// ---------------- TF32 tensor-core GEMM --------------------------------------
// C = act(A[M,K] @ W[K,N] + bias) (+ res).  Block 128x64, BK=32, 256 threads.
// 8 warps in 4(M)x2(N), each warp 32x32 = 2x2 wmma 16x16x8 tf32 tiles.
#define BM 128
#define BN 64
#define BK 32
#define APAD 36
#define BPAD 68

__device__ __forceinline__ float4 tf32x4(float4 v) {
    v.x = wmma::__float_to_tf32(v.x);
    v.y = wmma::__float_to_tf32(v.y);
    v.z = wmma::__float_to_tf32(v.z);
    v.w = wmma::__float_to_tf32(v.w);
    return v;
}

__global__ __launch_bounds__(256)
void gemm_tc_kernel(const float* __restrict__ A,
                    const float* __restrict__ W,
                    const float* __restrict__ bias,
                    const float* __restrict__ res,
                    float* __restrict__ C,
                    int M, int N, int K, int act) {
    __shared__ float sm[BM * BPAD];          // 8704 floats: C tile, aliases A+B
    float* As = sm;                          // [BM][APAD]  4608 floats
    float* Bs = sm + BM * APAD;              // [BK][BPAD]  2176 floats

    const int t = threadIdx.x;
    const int wid = t >> 5;
    const int wm0 = (wid & 3) * 32;
    const int wn0 = (wid >> 2) * 32;
    const int m0 = blockIdx.y * BM, n0 = blockIdx.x * BN;

    // A staging: thread covers rows ar, ar+32, ar+64, ar+96, cols ac..ac+3
    const int ar = t >> 3, ac = (t & 7) * 4;
    // B staging: rows br, br+16, cols bc..bc+3
    const int br = t >> 4, bc = (t & 15) * 4;

    wmma::fragment<wmma::accumulator, 16, 16, 8, float> acc[2][2];
    #pragma unroll
    for (int i = 0; i < 2; i++)
        #pragma unroll
        for (int j = 0; j < 2; j++)
            wmma::fill_fragment(acc[i][j], 0.0f);

    float4 ra[4], rb[2];
    // initial tile load
    #pragma unroll
    for (int i = 0; i < 4; i++)
        ra[i] = tf32x4(*(const float4*)(A + (size_t)(m0 + ar + 32 * i) * K + ac));
    #pragma unroll
    for (int i = 0; i < 2; i++)
        rb[i] = tf32x4(*(const float4*)(W + (size_t)(br + 16 * i) * N + n0 + bc));
    #pragma unroll
    for (int i = 0; i < 4; i++)
        *(float4*)(As + (ar + 32 * i) * APAD + ac) = ra[i];
    #pragma unroll
    for (int i = 0; i < 2; i++)
        *(float4*)(Bs + (br + 16 * i) * BPAD + bc) = rb[i];
    __syncthreads();

    for (int k0 = BK; k0 <= K; k0 += BK) {
        if (k0 < K) {   // prefetch next tile into registers
            #pragma unroll
            for (int i = 0; i < 4; i++)
                ra[i] = tf32x4(*(const float4*)(A + (size_t)(m0 + ar + 32 * i) * K + k0 + ac));
            #pragma unroll
            for (int i = 0; i < 2; i++)
                rb[i] = tf32x4(*(const float4*)(W + (size_t)(k0 + br + 16 * i) * N + n0 + bc));
        }
        // compute on current smem tile
        #pragma unroll
        for (int kk = 0; kk < BK; kk += 8) {
            wmma::fragment<wmma::matrix_a, 16, 16, 8, wmma::precision::tf32, wmma::row_major> af[2];
            wmma::fragment<wmma::matrix_b, 16, 16, 8, wmma::precision::tf32, wmma::row_major> bf[2];
            #pragma unroll
            for (int i = 0; i < 2; i++)
                wmma::load_matrix_sync(af[i], As + (wm0 + 16 * i) * APAD + kk, APAD);
            #pragma unroll
            for (int j = 0; j < 2; j++)
                wmma::load_matrix_sync(bf[j], Bs + kk * BPAD + wn0 + 16 * j, BPAD);
            #pragma unroll
            for (int i = 0; i < 2; i++)
                #pragma unroll
                for (int j = 0; j < 2; j++)
                    wmma::mma_sync(acc[i][j], af[i], bf[j], acc[i][j]);
        }
        __syncthreads();
        if (k0 < K) {
            #pragma unroll
            for (int i = 0; i < 4; i++)
                *(float4*)(As + (ar + 32 * i) * APAD + ac) = ra[i];
            #pragma unroll
            for (int i = 0; i < 2; i++)
                *(float4*)(Bs + (br + 16 * i) * BPAD + bc) = rb[i];
            __syncthreads();
        }
    }

    // epilogue via smem round-trip: Cs[BM][BPAD]
    #pragma unroll
    for (int i = 0; i < 2; i++)
        #pragma unroll
        for (int j = 0; j < 2; j++)
            wmma::store_matrix_sync(sm + (wm0 + 16 * i) * BPAD + wn0 + 16 * j,
                                    acc[i][j], BPAD, wmma::mem_row_major);
    __syncthreads();

    const int cr = t >> 4, cc = (t & 15) * 4;
    float4 bb = *(const float4*)(bias + n0 + cc);
    #pragma unroll
    for (int i = 0; i < 8; i++) {
        int m = m0 + cr + 16 * i;
        float4 v = *(const float4*)(sm + (cr + 16 * i) * BPAD + cc);
        v.x += bb.x; v.y += bb.y; v.z += bb.z; v.w += bb.w;
        if (act == 1) {
            v.x = 0.5f * v.x * (1.0f + erff(v.x * 0.70710678118654752f));
            v.y = 0.5f * v.y * (1.0f + erff(v.y * 0.70710678118654752f));
            v.z = 0.5f * v.z * (1.0f + erff(v.z * 0.70710678118654752f));
            v.w = 0.5f * v.w * (1.0f + erff(v.w * 0.70710678118654752f));
        }
        if (res) {
            float4 rv = *(const float4*)(res + (size_t)m * N + n0 + cc);
            v.x += rv.x; v.y += rv.y; v.z += rv.z; v.w += rv.w;
        }
        *(float4*)(C + (size_t)m * N + n0 + cc) = v;
    }
}

// ---------------- Flash attention with causal band mask ----------------------
// grid (T/64, H), 256 threads. BQ=BK=64, Dh=64.
#define PADW 68
__global__ void attn_kernel(const float* __restrict__ q,
                            const float* __restrict__ k,
                            const float* __restrict__ v,
                            float* __restrict__ out, int bw) {
    extern __shared__ float smdyn[];
    float* Qt = smdyn;                 // [64][68]  (d, q)
    float* Kt = smdyn + 64 * PADW;     // [64][68]  (d, k)
    float* Pt = smdyn + 2 * 64 * PADW; // [64][68]  (k, q)
    float* Vs = smdyn + 3 * 64 * PADW; // [64][64]  (k, c)

    const int t = threadIdx.x;
    const int tx = t & 15, ty = t >> 4;
    const int q0 = blockIdx.x * 64;
    const int head = blockIdx.y;
    const float* qh = q + head * DH;
    const float* kh = k + head * DH;
    const float* vh = v + head * DH;

    #pragma unroll
    for (int it = 0; it < 4; it++) {
        int e = t + it * 256;
        int row = e >> 4, cs = (e & 15) * 4;
        float4 qv = *(const float4*)(qh + (size_t)(q0 + row) * D + cs);
        Qt[(cs + 0) * PADW + row] = qv.x * 0.125f;
        Qt[(cs + 1) * PADW + row] = qv.y * 0.125f;
        Qt[(cs + 2) * PADW + row] = qv.z * 0.125f;
        Qt[(cs + 3) * PADW + row] = qv.w * 0.125f;
    }

    float o[4][4] = {};
    float mrow[4] = {-1e30f, -1e30f, -1e30f, -1e30f};
    float lrow[4] = {};

    int kt0 = max(0, q0 - bw) >> 6;
    int kt1 = q0 >> 6;
    for (int kt = kt0; kt <= kt1; kt++) {
        int j0 = kt << 6;
        __syncthreads();
        #pragma unroll
        for (int it = 0; it < 4; it++) {
            int e = t + it * 256;
            int row = e >> 4, cs = (e & 15) * 4;
            float4 kv = *(const float4*)(kh + (size_t)(j0 + row) * D + cs);
            Kt[(cs + 0) * PADW + row] = kv.x;
            Kt[(cs + 1) * PADW + row] = kv.y;
            Kt[(cs + 2) * PADW + row] = kv.z;
            Kt[(cs + 3) * PADW + row] = kv.w;
            float4 vv = *(const float4*)(vh + (size_t)(j0 + row) * D + cs);
            *(float4*)&Vs[row * 64 + cs] = vv;
        }
        __syncthreads();

        float s[4][4] = {};
        #pragma unroll 8
        for (int d = 0; d < 64; d++) {
            float4 qa = *(const float4*)&Qt[d * PADW + 4 * ty];
            float4 kb = *(const float4*)&Kt[d * PADW + 4 * tx];
            float qr[4] = {qa.x, qa.y, qa.z, qa.w};
            float kr[4] = {kb.x, kb.y, kb.z, kb.w};
            #pragma unroll
            for (int i = 0; i < 4; i++)
                #pragma unroll
                for (int j = 0; j < 4; j++)
                    s[i][j] += qr[i] * kr[j];
        }
        #pragma unroll
        for (int i = 0; i < 4; i++) {
            int qi = q0 + 4 * ty + i;
            #pragma unroll
            for (int j = 0; j < 4; j++) {
                int kj = j0 + 4 * tx + j;
                if (kj > qi || kj < qi - bw) s[i][j] = -1e30f;
            }
        }
        #pragma unroll
        for (int i = 0; i < 4; i++) {
            float mx = fmaxf(fmaxf(s[i][0], s[i][1]), fmaxf(s[i][2], s[i][3]));
            #pragma unroll
            for (int off = 1; off < 16; off <<= 1)
                mx = fmaxf(mx, __shfl_xor_sync(0xffffffffu, mx, off));
            float mn = fmaxf(mrow[i], mx);
            float alpha = __expf(mrow[i] - mn);
            float p[4];
            float rs = 0.f;
            #pragma unroll
            for (int j = 0; j < 4; j++) {
                p[j] = (s[i][j] < -1e29f) ? 0.f : __expf(s[i][j] - mn);
                rs += p[j];
            }
            #pragma unroll
            for (int off = 1; off < 16; off <<= 1)
                rs += __shfl_xor_sync(0xffffffffu, rs, off);
            mrow[i] = mn;
            lrow[i] = lrow[i] * alpha + rs;
            #pragma unroll
            for (int j = 0; j < 4; j++) o[i][j] *= alpha;
            #pragma unroll
            for (int j = 0; j < 4; j++)
                Pt[(4 * tx + j) * PADW + 4 * ty + i] = p[j];
        }
        __syncthreads();
        #pragma unroll 8
        for (int kk = 0; kk < 64; kk++) {
            float4 pa = *(const float4*)&Pt[kk * PADW + 4 * ty];
            float4 vb = *(const float4*)&Vs[kk * 64 + 4 * tx];
            float pr[4] = {pa.x, pa.y, pa.z, pa.w};
            float vr[4] = {vb.x, vb.y, vb.z, vb.w};
            #pragma unroll
            for (int i = 0; i < 4; i++)
                #pragma unroll
                for (int j = 0; j < 4; j++)
                    o[i][j] += pr[i] * vr[j];
        }
    }
    #pragma unroll
    for (int i = 0; i < 4; i++) {
        float inv = 1.0f / lrow[i];
        float4 r = {o[i][0] * inv, o[i][1] * inv, o[i][2] * inv, o[i][3] * inv};
        *(float4*)(out + (size_t)(q0 + 4 * ty + i) * D + head * DH + 4 * tx) = r;
    }
}

// ---------------- host orchestration ----------------------------------------
extern "C" void kernel_launch(void* const* d_in, const int* in_sizes, int n_in,
                              void* d_out, int out_size) {
    const float* x      = (const float*)d_in[0];
    const float* pos    = (const float*)d_in[1];
    const float* ln1_w  = (const float*)d_in[2];
    const float* ln1_b  = (const float*)d_in[3];
    const float* ln2_w  = (const float*)d_in[4];
    const float* ln2_b  = (const float*)d_in[5];
    const float* Wq     = (const float*)d_in[6];
    const float* bq     = (const float*)d_in[7];
    const float* Wk     = (const float*)d_in[8];
    const float* bk     = (const float*)d_in[9];
    const float* Wv     = (const float*)d_in[10];
    const float* bv     = (const float*)d_in[11];
    const float* Wo     = (const float*)d_in[12];
    const float* bo     = (const float*)d_in[13];
    const float* W1     = (const float*)d_in[14];
    const float* b1     = (const float*)d_in[15];
    const float* W2     = (const float*)d_in[16];
    const float* b2     = (const float*)d_in[17];
    const float* lnf_w  = (const float*)d_in[18];
    const float* lnf_b  = (const float*)d_in[19];
    float* out = (float*)d_out;

    float *ph, *pln, *pq, *pk, *pv, *pa, *pf;
    cudaGetSymbolAddress((void**)&ph,  g_h);
    cudaGetSymbolAddress((void**)&pln, g_ln);
    cudaGetSymbolAddress((void**)&pq,  g_q);
    cudaGetSymbolAddress((void**)&pk,  g_k);
    cudaGetSymbolAddress((void**)&pv,  g_v);
    cudaGetSymbolAddress((void**)&pa,  g_att);
    cudaGetSymbolAddress((void**)&pf,  g_ff);

    const int attn_smem = (3 * 64 * PADW + 64 * 64) * (int)sizeof(float); // 68608
    cudaFuncSetAttribute(attn_kernel,
                         cudaFuncAttributeMaxDynamicSharedMemorySize, attn_smem);

    const int bands[2] = {999, 9};
    for (int s = 0; s < 2; s++) {
        add_pos_kernel<<<T * D / 4 / 256, 256>>>(x, pos, ph);
        for (int l = 0; l < NL; l++) {
            int wi = s * NL + l;
            const float* pWq = Wq + (size_t)wi * D * D;
            const float* pWk = Wk + (size_t)wi * D * D;
            const float* pWv = Wv + (size_t)wi * D * D;
            const float* pWo = Wo + (size_t)wi * D * D;
            const float* pW1 = W1 + (size_t)wi * D * FF;
            const float* pW2 = W2 + (size_t)wi * FF * D;

            ln_kernel<<<T, 128>>>(ph, ln1_w + wi * D, ln1_b + wi * D, pln);

            dim3 g8(D / BN, T / BM);
            gemm_tc_kernel<<<g8, 256>>>(pln, pWq, bq + wi * D, nullptr, pq, T, D, D, 0);
            gemm_tc_kernel<<<g8, 256>>>(pln, pWk, bk + wi * D, nullptr, pk, T, D, D, 0);
            gemm_tc_kernel<<<g8, 256>>>(pln, pWv, bv + wi * D, nullptr, pv, T, D, D, 0);

            attn_kernel<<<dim3(T / 64, H), 256, attn_smem>>>(pq, pk, pv, pa, bands[s]);

            gemm_tc_kernel<<<g8, 256>>>(pa, pWo, bo + wi * D, ph, ph, T, D, D, 0);

            ln_kernel<<<T, 128>>>(ph, ln2_w + wi * D, ln2_b + wi * D, pln);

            dim3 g16(FF / BN, T / BM);
            gemm_tc_kernel<<<g16, 256>>>(pln, pW1, b1 + wi * FF, nullptr, pf, T, FF, D, 1);
            gemm_tc_kernel<<<g8, 256>>>(pf, pW2, b2 + wi * D, ph, ph, T, D, FF, 0);
        }
        ln_kernel<<<T, 128>>>(ph, lnf_w, lnf_b, out + (size_t)s * T * D);
    }
}

// round 7
// speedup vs baseline: 1.6725x; 1.3091x over previous
#include <cuda_runtime.h>
#include <cstdint>
#include <cstddef>
#include <mma.h>
#include <math.h>

using namespace nvcuda;

#define T 2048
#define D 512
#define H 8
#define DH 64
#define NL 2
#define FF 1024

// ---------------- scratch (per-stack: 2x) -----------------------------------
__device__ float g_h  [2 * T * D];
__device__ float g_ln [2 * T * D];
__device__ float g_q  [2 * T * D];
__device__ float g_k  [2 * T * D];
__device__ float g_v  [2 * T * D];
__device__ float g_att[2 * T * D];
__device__ float g_ff [2 * T * FF];

// ---------------- cp.async helpers -------------------------------------------
__device__ __forceinline__ void cp_async16(unsigned smem, const void* gmem) {
    asm volatile("cp.async.cg.shared.global [%0], [%1], 16;\n" :: "r"(smem), "l"(gmem));
}
__device__ __forceinline__ void cp_commit() {
    asm volatile("cp.async.commit_group;\n");
}
template<int N>
__device__ __forceinline__ void cp_wait() {
    asm volatile("cp.async.wait_group %0;\n" :: "n"(N));
}

// ---------------- x + pos -> both stacks -------------------------------------
__global__ void add_pos_kernel(const float* __restrict__ x,
                               const float* __restrict__ pos,
                               float* __restrict__ out) {
    int i = blockIdx.x * blockDim.x + threadIdx.x;   // float4 index
    float4 a = ((const float4*)x)[i];
    float4 b = ((const float4*)pos)[i];
    a.x += b.x; a.y += b.y; a.z += b.z; a.w += b.w;
    ((float4*)out)[i] = a;
    ((float4*)(out + T * D))[i] = a;
}

// ---------------- batched LayerNorm (grid.y = stack) -------------------------
__global__ void ln_kernel(const float* __restrict__ x,
                          const float* __restrict__ w, int ws,
                          const float* __restrict__ b, int bs,
                          float* __restrict__ out) {
    int s = blockIdx.y;
    int row = blockIdx.x;
    int t = threadIdx.x;  // 128 threads, 4 floats each
    const float* xr = x + (size_t)s * T * D + row * D;
    const float* wp = w + (size_t)s * ws;
    const float* bp = b + (size_t)s * bs;
    float4 v = *(const float4*)(xr + t * 4);
    float sm_ = v.x + v.y + v.z + v.w;
    float ss = v.x * v.x + v.y * v.y + v.z * v.z + v.w * v.w;
    #pragma unroll
    for (int o = 16; o > 0; o >>= 1) {
        sm_ += __shfl_xor_sync(0xffffffffu, sm_, o);
        ss  += __shfl_xor_sync(0xffffffffu, ss, o);
    }
    __shared__ float sh[8];
    int wid = t >> 5, lane = t & 31;
    if (lane == 0) { sh[wid] = sm_; sh[4 + wid] = ss; }
    __syncthreads();
    float S  = sh[0] + sh[1] + sh[2] + sh[3];
    float SS = sh[4] + sh[5] + sh[6] + sh[7];
    float mu = S * (1.0f / D);
    float var = SS * (1.0f / D) - mu * mu;
    float rstd = rsqrtf(var + 1e-5f);
    float4 wv = *(const float4*)(wp + t * 4);
    float4 bv = *(const float4*)(bp + t * 4);
    float4 r;
    r.x = (v.x - mu) * rstd * wv.x + bv.x;
    r.y = (v.y - mu) * rstd * wv.y + bv.y;
    r.z = (v.z - mu) * rstd * wv.z + bv.z;
    r.w = (v.w - mu) * rstd * wv.w + bv.w;
    *(float4*)(out + (size_t)s * T * D + row * D + t * 4) = r;
}

// ---------------- TF32 tensor-core GEMM, cp.async 3-stage --------------------
// C = act(A @ W + bias) (+res). Block 64x64, BK=32, 128 threads (4 warps 2x2).
// blockIdx.z = stack; all pointers get per-stack strides.
#define GBM 64
#define GBN 64
#define GBK 32
#define GAPAD 36
#define GBPAD 68
#define GSTG 3
#define STAGE_F (GBM * GAPAD + GBK * GBPAD)   // 4480 floats per stage

__global__ __launch_bounds__(128)
void gemm_tc_kernel(const float* __restrict__ A,  size_t aS,
                    const float* __restrict__ W,  size_t wS,
                    const float* __restrict__ bias, size_t biasS,
                    const float* __restrict__ res,  size_t resS,
                    float* __restrict__ C, size_t cS,
                    int N, int K, int act) {
    __shared__ float sm[GSTG * STAGE_F];

    const int s = blockIdx.z;
    A = A + s * aS;  W = W + s * wS;  bias = bias + s * biasS;
    if (res) res = res + s * resS;
    C = C + s * cS;

    const int t = threadIdx.x;
    const int wid = t >> 5;
    const int wm0 = (wid & 1) * 32;
    const int wn0 = (wid >> 1) * 32;
    const int m0 = blockIdx.y * GBM, n0 = blockIdx.x * GBN;

    const unsigned smem_base = (unsigned)__cvta_generic_to_shared(sm);

    const int NITER = K / GBK;

    // per-thread staging coords (4 x 16B chunks for A, 4 for B)
    auto load_stage = [&](int stg, int iter) {
        unsigned base = smem_base + stg * STAGE_F * 4;
        int k0 = iter * GBK;
        #pragma unroll
        for (int i = 0; i < 4; i++) {
            int c = t + i * 128;
            int rowa = c >> 3, cola = (c & 7) * 4;
            cp_async16(base + (rowa * GAPAD + cola) * 4,
                       A + (size_t)(m0 + rowa) * K + k0 + cola);
        }
        unsigned bbase = base + GBM * GAPAD * 4;
        #pragma unroll
        for (int i = 0; i < 4; i++) {
            int c = t + i * 128;
            int rowb = c >> 4, colb = (c & 15) * 4;
            cp_async16(bbase + (rowb * GBPAD + colb) * 4,
                       W + (size_t)(k0 + rowb) * N + n0 + colb);
        }
    };

    wmma::fragment<wmma::accumulator, 16, 16, 8, float> acc[2][2];
    #pragma unroll
    for (int i = 0; i < 2; i++)
        #pragma unroll
        for (int j = 0; j < 2; j++)
            wmma::fill_fragment(acc[i][j], 0.0f);

    #pragma unroll
    for (int p = 0; p < GSTG - 1; p++) { load_stage(p, p); cp_commit(); }

    for (int it = 0; it < NITER; it++) {
        cp_wait<GSTG - 2>();
        __syncthreads();
        if (it + GSTG - 1 < NITER) load_stage((it + GSTG - 1) % GSTG, it + GSTG - 1);
        cp_commit();

        const float* As = sm + (it % GSTG) * STAGE_F;
        const float* Bs = As + GBM * GAPAD;
        #pragma unroll
        for (int kk = 0; kk < GBK; kk += 8) {
            wmma::fragment<wmma::matrix_a, 16, 16, 8, wmma::precision::tf32, wmma::row_major> af[2];
            wmma::fragment<wmma::matrix_b, 16, 16, 8, wmma::precision::tf32, wmma::row_major> bf[2];
            #pragma unroll
            for (int i = 0; i < 2; i++)
                wmma::load_matrix_sync(af[i], As + (wm0 + 16 * i) * GAPAD + kk, GAPAD);
            #pragma unroll
            for (int j = 0; j < 2; j++)
                wmma::load_matrix_sync(bf[j], Bs + kk * GBPAD + wn0 + 16 * j, GBPAD);
            #pragma unroll
            for (int i = 0; i < 2; i++)
                #pragma unroll
                for (int j = 0; j < 2; j++)
                    wmma::mma_sync(acc[i][j], af[i], bf[j], acc[i][j]);
        }
    }

    // epilogue: accs -> smem -> global with bias/act/residual
    __syncthreads();
    #pragma unroll
    for (int i = 0; i < 2; i++)
        #pragma unroll
        for (int j = 0; j < 2; j++)
            wmma::store_matrix_sync(sm + (wm0 + 16 * i) * GBPAD + wn0 + 16 * j,
                                    acc[i][j], GBPAD, wmma::mem_row_major);
    __syncthreads();

    const int cr = t >> 4, cc = (t & 15) * 4;  // 8 rows x 16 col-chunks
    float4 bb = *(const float4*)(bias + n0 + cc);
    #pragma unroll
    for (int i = 0; i < 8; i++) {
        int r = cr + 8 * i;
        int m = m0 + r;
        float4 v = *(const float4*)(sm + r * GBPAD + cc);
        v.x += bb.x; v.y += bb.y; v.z += bb.z; v.w += bb.w;
        if (act == 1) {
            v.x = 0.5f * v.x * (1.0f + erff(v.x * 0.70710678118654752f));
            v.y = 0.5f * v.y * (1.0f + erff(v.y * 0.70710678118654752f));
            v.z = 0.5f * v.z * (1.0f + erff(v.z * 0.70710678118654752f));
            v.w = 0.5f * v.w * (1.0f + erff(v.w * 0.70710678118654752f));
        }
        if (res) {
            float4 rv = *(const float4*)(res + (size_t)m * N + n0 + cc);
            v.x += rv.x; v.y += rv.y; v.z += rv.z; v.w += rv.w;
        }
        *(float4*)(C + (size_t)m * N + n0 + cc) = v;
    }
}

// ---------------- Flash attention, batched over stacks -----------------------
// grid (T/64, H, 2), 256 threads. BQ=BK=64, Dh=64.
#define PADW 68
__global__ void attn_kernel(const float* __restrict__ q,
                            const float* __restrict__ k,
                            const float* __restrict__ v,
                            float* __restrict__ out) {
    extern __shared__ float smdyn[];
    float* Qt = smdyn;                 // [64][68]  (d, q)
    float* Kt = smdyn + 64 * PADW;     // [64][68]  (d, k)
    float* Pt = smdyn + 2 * 64 * PADW; // [64][68]  (k, q)
    float* Vs = smdyn + 3 * 64 * PADW; // [64][64]  (k, c)

    const int t = threadIdx.x;
    const int tx = t & 15, ty = t >> 4;
    const int q0 = blockIdx.x * 64;
    const int head = blockIdx.y;
    const int stk = blockIdx.z;
    const int bw = stk == 0 ? 999 : 9;
    const size_t sb = (size_t)stk * T * D;
    const float* qh = q + sb + head * DH;
    const float* kh = k + sb + head * DH;
    const float* vh = v + sb + head * DH;

    #pragma unroll
    for (int it = 0; it < 4; it++) {
        int e = t + it * 256;
        int row = e >> 4, cs = (e & 15) * 4;
        float4 qv = *(const float4*)(qh + (size_t)(q0 + row) * D + cs);
        Qt[(cs + 0) * PADW + row] = qv.x * 0.125f;
        Qt[(cs + 1) * PADW + row] = qv.y * 0.125f;
        Qt[(cs + 2) * PADW + row] = qv.z * 0.125f;
        Qt[(cs + 3) * PADW + row] = qv.w * 0.125f;
    }

    float o[4][4] = {};
    float mrow[4] = {-1e30f, -1e30f, -1e30f, -1e30f};
    float lrow[4] = {};

    int kt0 = max(0, q0 - bw) >> 6;
    int kt1 = q0 >> 6;
    for (int kt = kt0; kt <= kt1; kt++) {
        int j0 = kt << 6;
        __syncthreads();
        #pragma unroll
        for (int it = 0; it < 4; it++) {
            int e = t + it * 256;
            int row = e >> 4, cs = (e & 15) * 4;
            float4 kv = *(const float4*)(kh + (size_t)(j0 + row) * D + cs);
            Kt[(cs + 0) * PADW + row] = kv.x;
            Kt[(cs + 1) * PADW + row] = kv.y;
            Kt[(cs + 2) * PADW + row] = kv.z;
            Kt[(cs + 3) * PADW + row] = kv.w;
            float4 vv = *(const float4*)(vh + (size_t)(j0 + row) * D + cs);
            *(float4*)&Vs[row * 64 + cs] = vv;
        }
        __syncthreads();

        float s[4][4] = {};
        #pragma unroll 8
        for (int d = 0; d < 64; d++) {
            float4 qa = *(const float4*)&Qt[d * PADW + 4 * ty];
            float4 kb = *(const float4*)&Kt[d * PADW + 4 * tx];
            float qr[4] = {qa.x, qa.y, qa.z, qa.w};
            float kr[4] = {kb.x, kb.y, kb.z, kb.w};
            #pragma unroll
            for (int i = 0; i < 4; i++)
                #pragma unroll
                for (int j = 0; j < 4; j++)
                    s[i][j] += qr[i] * kr[j];
        }
        #pragma unroll
        for (int i = 0; i < 4; i++) {
            int qi = q0 + 4 * ty + i;
            #pragma unroll
            for (int j = 0; j < 4; j++) {
                int kj = j0 + 4 * tx + j;
                if (kj > qi || kj < qi - bw) s[i][j] = -1e30f;
            }
        }
        #pragma unroll
        for (int i = 0; i < 4; i++) {
            float mx = fmaxf(fmaxf(s[i][0], s[i][1]), fmaxf(s[i][2], s[i][3]));
            #pragma unroll
            for (int off = 1; off < 16; off <<= 1)
                mx = fmaxf(mx, __shfl_xor_sync(0xffffffffu, mx, off));
            float mn = fmaxf(mrow[i], mx);
            float alpha = __expf(mrow[i] - mn);
            float p[4];
            float rs = 0.f;
            #pragma unroll
            for (int j = 0; j < 4; j++) {
                p[j] = (s[i][j] < -1e29f) ? 0.f : __expf(s[i][j] - mn);
                rs += p[j];
            }
            #pragma unroll
            for (int off = 1; off < 16; off <<= 1)
                rs += __shfl_xor_sync(0xffffffffu, rs, off);
            mrow[i] = mn;
            lrow[i] = lrow[i] * alpha + rs;
            #pragma unroll
            for (int j = 0; j < 4; j++) o[i][j] *= alpha;
            #pragma unroll
            for (int j = 0; j < 4; j++)
                Pt[(4 * tx + j) * PADW + 4 * ty + i] = p[j];
        }
        __syncthreads();
        #pragma unroll 8
        for (int kk = 0; kk < 64; kk++) {
            float4 pa = *(const float4*)&Pt[kk * PADW + 4 * ty];
            float4 vb = *(const float4*)&Vs[kk * 64 + 4 * tx];
            float pr[4] = {pa.x, pa.y, pa.z, pa.w};
            float vr[4] = {vb.x, vb.y, vb.z, vb.w};
            #pragma unroll
            for (int i = 0; i < 4; i++)
                #pragma unroll
                for (int j = 0; j < 4; j++)
                    o[i][j] += pr[i] * vr[j];
        }
    }
    #pragma unroll
    for (int i = 0; i < 4; i++) {
        float inv = 1.0f / lrow[i];
        float4 r = {o[i][0] * inv, o[i][1] * inv, o[i][2] * inv, o[i][3] * inv};
        *(float4*)(out + sb + (size_t)(q0 + 4 * ty + i) * D + head * DH + 4 * tx) = r;
    }
}

// ---------------- host orchestration ----------------------------------------
extern "C" void kernel_launch(void* const* d_in, const int* in_sizes, int n_in,
                              void* d_out, int out_size) {
    const float* x      = (const float*)d_in[0];
    const float* pos    = (const float*)d_in[1];
    const float* ln1_w  = (const float*)d_in[2];
    const float* ln1_b  = (const float*)d_in[3];
    const float* ln2_w  = (const float*)d_in[4];
    const float* ln2_b  = (const float*)d_in[5];
    const float* Wq     = (const float*)d_in[6];
    const float* bq     = (const float*)d_in[7];
    const float* Wk     = (const float*)d_in[8];
    const float* bk     = (const float*)d_in[9];
    const float* Wv     = (const float*)d_in[10];
    const float* bv     = (const float*)d_in[11];
    const float* Wo     = (const float*)d_in[12];
    const float* bo     = (const float*)d_in[13];
    const float* W1     = (const float*)d_in[14];
    const float* b1     = (const float*)d_in[15];
    const float* W2     = (const float*)d_in[16];
    const float* b2     = (const float*)d_in[17];
    const float* lnf_w  = (const float*)d_in[18];
    const float* lnf_b  = (const float*)d_in[19];
    float* out = (float*)d_out;

    float *ph, *pln, *pq, *pk, *pv, *pa, *pf;
    cudaGetSymbolAddress((void**)&ph,  g_h);
    cudaGetSymbolAddress((void**)&pln, g_ln);
    cudaGetSymbolAddress((void**)&pq,  g_q);
    cudaGetSymbolAddress((void**)&pk,  g_k);
    cudaGetSymbolAddress((void**)&pv,  g_v);
    cudaGetSymbolAddress((void**)&pa,  g_att);
    cudaGetSymbolAddress((void**)&pf,  g_ff);

    const int attn_smem = (3 * 64 * PADW + 64 * 64) * (int)sizeof(float); // 68608
    cudaFuncSetAttribute(attn_kernel,
                         cudaFuncAttributeMaxDynamicSharedMemorySize, attn_smem);

    const size_t SD   = (size_t)T * D;        // per-stack activation stride
    const size_t SF   = (size_t)T * FF;
    const size_t WS   = (size_t)NL * D * D;   // per-stack weight stride (layer fixed)
    const size_t W1S  = (size_t)NL * D * FF;
    const size_t BS   = (size_t)NL * D;       // per-stack bias / ln stride
    const size_t B1S  = (size_t)NL * FF;

    add_pos_kernel<<<T * D / 4 / 256, 256>>>(x, pos, ph);

    for (int l = 0; l < NL; l++) {
        const size_t wo  = (size_t)l * D * D;
        const size_t w1o = (size_t)l * D * FF;
        const size_t w2o = (size_t)l * FF * D;
        const size_t bo_ = (size_t)l * D;
        const size_t b1o = (size_t)l * FF;

        ln_kernel<<<dim3(T, 2), 128>>>(ph, ln1_w + bo_, (int)BS, ln1_b + bo_, (int)BS, pln);

        dim3 g8(D / GBN, T / GBM, 2);
        gemm_tc_kernel<<<g8, 128>>>(pln, SD, Wq + wo, WS, bq + bo_, BS, nullptr, 0, pq, SD, D, D, 0);
        gemm_tc_kernel<<<g8, 128>>>(pln, SD, Wk + wo, WS, bk + bo_, BS, nullptr, 0, pk, SD, D, D, 0);
        gemm_tc_kernel<<<g8, 128>>>(pln, SD, Wv + wo, WS, bv + bo_, BS, nullptr, 0, pv, SD, D, D, 0);

        attn_kernel<<<dim3(T / 64, H, 2), 256, attn_smem>>>(pq, pk, pv, pa);

        gemm_tc_kernel<<<g8, 128>>>(pa, SD, Wo + wo, WS, bo + bo_, BS, ph, SD, ph, SD, D, D, 0);

        ln_kernel<<<dim3(T, 2), 128>>>(ph, ln2_w + bo_, (int)BS, ln2_b + bo_, (int)BS, pln);

        dim3 g16(FF / GBN, T / GBM, 2);
        gemm_tc_kernel<<<g16, 128>>>(pln, SD, W1 + w1o, W1S, b1 + b1o, B1S, nullptr, 0, pf, SF, FF, D, 1);
        gemm_tc_kernel<<<g8, 128>>>(pf, SF, W2 + w2o, W1S, b2 + bo_, BS, ph, SD, ph, SD, D, FF, 0);
    }
    // final LN: same weights for both stacks (stride 0); out is [2][T][D]
    ln_kernel<<<dim3(T, 2), 128>>>(ph, lnf_w, 0, lnf_b, 0, out);
}

// round 9
// speedup vs baseline: 1.7643x; 1.0549x over previous
#include <cuda_runtime.h>
#include <cstdint>
#include <cstddef>
#include <mma.h>
#include <math.h>

using namespace nvcuda;

#define T 2048
#define D 512
#define H 8
#define DH 64
#define NL 2
#define FF 1024

// ---------------- scratch (per-stack: 2x) -----------------------------------
__device__ float g_h  [2 * T * D];
__device__ float g_ln [2 * T * D];
__device__ float g_q  [2 * T * D];
__device__ float g_k  [2 * T * D];
__device__ float g_v  [2 * T * D];
__device__ float g_att[2 * T * D];
__device__ float g_ff [2 * T * FF];

// ---------------- cp.async helpers -------------------------------------------
__device__ __forceinline__ void cp_async16(unsigned smem, const void* gmem) {
    asm volatile("cp.async.cg.shared.global [%0], [%1], 16;\n" :: "r"(smem), "l"(gmem));
}
__device__ __forceinline__ void cp_commit() {
    asm volatile("cp.async.commit_group;\n");
}
template<int N>
__device__ __forceinline__ void cp_wait() {
    asm volatile("cp.async.wait_group %0;\n" :: "n"(N));
}

// ---------------- x + pos -> both stacks -------------------------------------
__global__ void add_pos_kernel(const float* __restrict__ x,
                               const float* __restrict__ pos,
                               float* __restrict__ out) {
    int i = blockIdx.x * blockDim.x + threadIdx.x;   // float4 index
    float4 a = ((const float4*)x)[i];
    float4 b = ((const float4*)pos)[i];
    a.x += b.x; a.y += b.y; a.z += b.z; a.w += b.w;
    ((float4*)out)[i] = a;
    ((float4*)(out + T * D))[i] = a;
}

// ---------------- batched LayerNorm (grid.y = stack) -------------------------
__global__ void ln_kernel(const float* __restrict__ x,
                          const float* __restrict__ w, int ws,
                          const float* __restrict__ b, int bs,
                          float* __restrict__ out) {
    int s = blockIdx.y;
    int row = blockIdx.x;
    int t = threadIdx.x;  // 128 threads, 4 floats each
    const float* xr = x + (size_t)s * T * D + row * D;
    const float* wp = w + (size_t)s * ws;
    const float* bp = b + (size_t)s * bs;
    float4 v = *(const float4*)(xr + t * 4);
    float sm_ = v.x + v.y + v.z + v.w;
    float ss = v.x * v.x + v.y * v.y + v.z * v.z + v.w * v.w;
    #pragma unroll
    for (int o = 16; o > 0; o >>= 1) {
        sm_ += __shfl_xor_sync(0xffffffffu, sm_, o);
        ss  += __shfl_xor_sync(0xffffffffu, ss, o);
    }
    __shared__ float sh[8];
    int wid = t >> 5, lane = t & 31;
    if (lane == 0) { sh[wid] = sm_; sh[4 + wid] = ss; }
    __syncthreads();
    float S  = sh[0] + sh[1] + sh[2] + sh[3];
    float SS = sh[4] + sh[5] + sh[6] + sh[7];
    float mu = S * (1.0f / D);
    float var = SS * (1.0f / D) - mu * mu;
    float rstd = rsqrtf(var + 1e-5f);
    float4 wv = *(const float4*)(wp + t * 4);
    float4 bv = *(const float4*)(bp + t * 4);
    float4 r;
    r.x = (v.x - mu) * rstd * wv.x + bv.x;
    r.y = (v.y - mu) * rstd * wv.y + bv.y;
    r.z = (v.z - mu) * rstd * wv.z + bv.z;
    r.w = (v.w - mu) * rstd * wv.w + bv.w;
    *(float4*)(out + (size_t)s * T * D + row * D + t * 4) = r;
}

// ---------------- TF32 tensor-core GEMM core ---------------------------------
// Block tile 128x64, BK=32, 128 threads (4 warps, 2x2), warp tile 64x32.
// 3-stage cp.async pipeline, dynamic smem.
#define BM 128
#define BN 64
#define BK 32
#define APAD 36
#define BPAD 68
#define NSTG 3
#define STAGE_F (BM * APAD + BK * BPAD)   // 6784 floats / stage
#define GEMM_SMEM (NSTG * STAGE_F * 4)    // 81408 bytes

__device__ __forceinline__ void gemm_body(
    const float* __restrict__ A, const float* __restrict__ W,
    const float* __restrict__ bias, const float* __restrict__ res,
    float* __restrict__ C, int N, int K, int act,
    int m0, int n0, float* sm)
{
    const int t = threadIdx.x;
    const int wid = t >> 5;
    const int wm0 = (wid & 1) * 64;
    const int wn0 = (wid >> 1) * 32;
    const unsigned smem_base = (unsigned)__cvta_generic_to_shared(sm);
    const int NITER = K / BK;

    auto load_stage = [&](int stg, int iter) {
        unsigned base = smem_base + stg * STAGE_F * 4;
        int k0 = iter * BK;
        #pragma unroll
        for (int i = 0; i < 8; i++) {        // A: 128x32, 8 chunks/row
            int c = t + i * 128;
            int rowa = c >> 3, cola = (c & 7) * 4;
            cp_async16(base + (rowa * APAD + cola) * 4,
                       A + (size_t)(m0 + rowa) * K + k0 + cola);
        }
        unsigned bbase = base + BM * APAD * 4;
        #pragma unroll
        for (int i = 0; i < 4; i++) {        // B: 32x64, 16 chunks/row
            int c = t + i * 128;
            int rowb = c >> 4, colb = (c & 15) * 4;
            cp_async16(bbase + (rowb * BPAD + colb) * 4,
                       W + (size_t)(k0 + rowb) * N + n0 + colb);
        }
    };

    wmma::fragment<wmma::accumulator, 16, 16, 8, float> acc[4][2];
    #pragma unroll
    for (int i = 0; i < 4; i++)
        #pragma unroll
        for (int j = 0; j < 2; j++)
            wmma::fill_fragment(acc[i][j], 0.0f);

    #pragma unroll
    for (int p = 0; p < NSTG - 1; p++) { load_stage(p, p); cp_commit(); }

    for (int it = 0; it < NITER; it++) {
        cp_wait<NSTG - 2>();
        __syncthreads();
        if (it + NSTG - 1 < NITER) load_stage((it + NSTG - 1) % NSTG, it + NSTG - 1);
        cp_commit();

        const float* As = sm + (it % NSTG) * STAGE_F;
        const float* Bs = As + BM * APAD;
        #pragma unroll
        for (int kk = 0; kk < BK; kk += 8) {
            wmma::fragment<wmma::matrix_a, 16, 16, 8, wmma::precision::tf32, wmma::row_major> af[4];
            wmma::fragment<wmma::matrix_b, 16, 16, 8, wmma::precision::tf32, wmma::row_major> bf[2];
            #pragma unroll
            for (int i = 0; i < 4; i++)
                wmma::load_matrix_sync(af[i], As + (wm0 + 16 * i) * APAD + kk, APAD);
            #pragma unroll
            for (int j = 0; j < 2; j++)
                wmma::load_matrix_sync(bf[j], Bs + kk * BPAD + wn0 + 16 * j, BPAD);
            #pragma unroll
            for (int i = 0; i < 4; i++)
                #pragma unroll
                for (int j = 0; j < 2; j++)
                    wmma::mma_sync(acc[i][j], af[i], bf[j], acc[i][j]);
        }
    }

    // epilogue: accs -> smem -> global with bias/act/residual
    __syncthreads();
    #pragma unroll
    for (int i = 0; i < 4; i++)
        #pragma unroll
        for (int j = 0; j < 2; j++)
            wmma::store_matrix_sync(sm + (wm0 + 16 * i) * BPAD + wn0 + 16 * j,
                                    acc[i][j], BPAD, wmma::mem_row_major);
    __syncthreads();

    const int cr = t >> 4, cc = (t & 15) * 4;  // 8 rows/pass, 16 passes
    float4 bb = *(const float4*)(bias + n0 + cc);
    #pragma unroll
    for (int i = 0; i < 16; i++) {
        int r = cr + 8 * i;
        int m = m0 + r;
        float4 v = *(const float4*)(sm + r * BPAD + cc);
        v.x += bb.x; v.y += bb.y; v.z += bb.z; v.w += bb.w;
        if (act == 1) {
            v.x = 0.5f * v.x * (1.0f + erff(v.x * 0.70710678118654752f));
            v.y = 0.5f * v.y * (1.0f + erff(v.y * 0.70710678118654752f));
            v.z = 0.5f * v.z * (1.0f + erff(v.z * 0.70710678118654752f));
            v.w = 0.5f * v.w * (1.0f + erff(v.w * 0.70710678118654752f));
        }
        if (res) {
            float4 rv = *(const float4*)(res + (size_t)m * N + n0 + cc);
            v.x += rv.x; v.y += rv.y; v.z += rv.z; v.w += rv.w;
        }
        *(float4*)(C + (size_t)m * N + n0 + cc) = v;
    }
}

// generic GEMM: blockIdx.z = stack
__global__ __launch_bounds__(128)
void gemm_tc_kernel(const float* __restrict__ A,  size_t aS,
                    const float* __restrict__ W,  size_t wS,
                    const float* __restrict__ bias, size_t biasS,
                    const float* __restrict__ res,  size_t resS,
                    float* __restrict__ C, size_t cS,
                    int N, int K, int act) {
    extern __shared__ float sm[];
    const int s = blockIdx.z;
    gemm_body(A + s * aS, W + s * wS, bias + s * biasS,
              res ? res + s * resS : nullptr, C + s * cS,
              N, K, act,
              blockIdx.y * BM, blockIdx.x * BN, sm);
}

// fused QKV: blockIdx.z in 0..5 -> (which = z>>1, stack = z&1)
__global__ __launch_bounds__(128)
void gemm_qkv_kernel(const float* __restrict__ A,  size_t aS,
                     const float* __restrict__ W0,
                     const float* __restrict__ W1_,
                     const float* __restrict__ W2_, size_t wS,
                     const float* __restrict__ b0,
                     const float* __restrict__ b1_,
                     const float* __restrict__ b2_, size_t biasS,
                     float* __restrict__ C0,
                     float* __restrict__ C1,
                     float* __restrict__ C2, size_t cS) {
    extern __shared__ float sm[];
    const int z = blockIdx.z;
    const int which = z >> 1, s = z & 1;
    const float* W = (which == 0) ? W0 : (which == 1) ? W1_ : W2_;
    const float* bia = (which == 0) ? b0 : (which == 1) ? b1_ : b2_;
    float* C = (which == 0) ? C0 : (which == 1) ? C1 : C2;
    gemm_body(A + s * aS, W + s * wS, bia + s * biasS, nullptr, C + s * cS,
              D, D, 0,
              blockIdx.y * BM, blockIdx.x * BN, sm);
}

// ---------------- Flash attention, batched over stacks -----------------------
// grid (T/64, H, 2), 256 threads. BQ=BK=64, Dh=64.
#define PADW 68
__global__ void attn_kernel(const float* __restrict__ q,
                            const float* __restrict__ k,
                            const float* __restrict__ v,
                            float* __restrict__ out) {
    extern __shared__ float smdyn[];
    float* Qt = smdyn;                 // [64][68]  (d, q)
    float* Kt = smdyn + 64 * PADW;     // [64][68]  (d, k)
    float* Pt = smdyn + 2 * 64 * PADW; // [64][68]  (k, q)
    float* Vs = smdyn + 3 * 64 * PADW; // [64][64]  (k, c)

    const int t = threadIdx.x;
    const int tx = t & 15, ty = t >> 4;
    const int q0 = blockIdx.x * 64;
    const int head = blockIdx.y;
    const int stk = blockIdx.z;
    const int bw = stk == 0 ? 999 : 9;
    const size_t sb = (size_t)stk * T * D;
    const float* qh = q + sb + head * DH;
    const float* kh = k + sb + head * DH;
    const float* vh = v + sb + head * DH;

    #pragma unroll
    for (int it = 0; it < 4; it++) {
        int e = t + it * 256;
        int row = e >> 4, cs = (e & 15) * 4;
        float4 qv = *(const float4*)(qh + (size_t)(q0 + row) * D + cs);
        Qt[(cs + 0) * PADW + row] = qv.x * 0.125f;
        Qt[(cs + 1) * PADW + row] = qv.y * 0.125f;
        Qt[(cs + 2) * PADW + row] = qv.z * 0.125f;
        Qt[(cs + 3) * PADW + row] = qv.w * 0.125f;
    }

    float o[4][4] = {};
    float mrow[4] = {-1e30f, -1e30f, -1e30f, -1e30f};
    float lrow[4] = {};

    int kt0 = max(0, q0 - bw) >> 6;
    int kt1 = q0 >> 6;
    for (int kt = kt0; kt <= kt1; kt++) {
        int j0 = kt << 6;
        __syncthreads();
        #pragma unroll
        for (int it = 0; it < 4; it++) {
            int e = t + it * 256;
            int row = e >> 4, cs = (e & 15) * 4;
            float4 kv = *(const float4*)(kh + (size_t)(j0 + row) * D + cs);
            Kt[(cs + 0) * PADW + row] = kv.x;
            Kt[(cs + 1) * PADW + row] = kv.y;
            Kt[(cs + 2) * PADW + row] = kv.z;
            Kt[(cs + 3) * PADW + row] = kv.w;
            float4 vv = *(const float4*)(vh + (size_t)(j0 + row) * D + cs);
            *(float4*)&Vs[row * 64 + cs] = vv;
        }
        __syncthreads();

        float s[4][4] = {};
        #pragma unroll 8
        for (int d = 0; d < 64; d++) {
            float4 qa = *(const float4*)&Qt[d * PADW + 4 * ty];
            float4 kb = *(const float4*)&Kt[d * PADW + 4 * tx];
            float qr[4] = {qa.x, qa.y, qa.z, qa.w};
            float kr[4] = {kb.x, kb.y, kb.z, kb.w};
            #pragma unroll
            for (int i = 0; i < 4; i++)
                #pragma unroll
                for (int j = 0; j < 4; j++)
                    s[i][j] += qr[i] * kr[j];
        }
        #pragma unroll
        for (int i = 0; i < 4; i++) {
            int qi = q0 + 4 * ty + i;
            #pragma unroll
            for (int j = 0; j < 4; j++) {
                int kj = j0 + 4 * tx + j;
                if (kj > qi || kj < qi - bw) s[i][j] = -1e30f;
            }
        }
        #pragma unroll
        for (int i = 0; i < 4; i++) {
            float mx = fmaxf(fmaxf(s[i][0], s[i][1]), fmaxf(s[i][2], s[i][3]));
            #pragma unroll
            for (int off = 1; off < 16; off <<= 1)
                mx = fmaxf(mx, __shfl_xor_sync(0xffffffffu, mx, off));
            float mn = fmaxf(mrow[i], mx);
            float alpha = __expf(mrow[i] - mn);
            float p[4];
            float rs = 0.f;
            #pragma unroll
            for (int j = 0; j < 4; j++) {
                p[j] = (s[i][j] < -1e29f) ? 0.f : __expf(s[i][j] - mn);
                rs += p[j];
            }
            #pragma unroll
            for (int off = 1; off < 16; off <<= 1)
                rs += __shfl_xor_sync(0xffffffffu, rs, off);
            mrow[i] = mn;
            lrow[i] = lrow[i] * alpha + rs;
            #pragma unroll
            for (int j = 0; j < 4; j++) o[i][j] *= alpha;
            #pragma unroll
            for (int j = 0; j < 4; j++)
                Pt[(4 * tx + j) * PADW + 4 * ty + i] = p[j];
        }
        __syncthreads();
        #pragma unroll 8
        for (int kk = 0; kk < 64; kk++) {
            float4 pa = *(const float4*)&Pt[kk * PADW + 4 * ty];
            float4 vb = *(const float4*)&Vs[kk * 64 + 4 * tx];
            float pr[4] = {pa.x, pa.y, pa.z, pa.w};
            float vr[4] = {vb.x, vb.y, vb.z, vb.w};
            #pragma unroll
            for (int i = 0; i < 4; i++)
                #pragma unroll
                for (int j = 0; j < 4; j++)
                    o[i][j] += pr[i] * vr[j];
        }
    }
    #pragma unroll
    for (int i = 0; i < 4; i++) {
        float inv = 1.0f / lrow[i];
        float4 r = {o[i][0] * inv, o[i][1] * inv, o[i][2] * inv, o[i][3] * inv};
        *(float4*)(out + sb + (size_t)(q0 + 4 * ty + i) * D + head * DH + 4 * tx) = r;
    }
}

// ---------------- host orchestration ----------------------------------------
extern "C" void kernel_launch(void* const* d_in, const int* in_sizes, int n_in,
                              void* d_out, int out_size) {
    const float* x      = (const float*)d_in[0];
    const float* pos    = (const float*)d_in[1];
    const float* ln1_w  = (const float*)d_in[2];
    const float* ln1_b  = (const float*)d_in[3];
    const float* ln2_w  = (const float*)d_in[4];
    const float* ln2_b  = (const float*)d_in[5];
    const float* Wq     = (const float*)d_in[6];
    const float* bq     = (const float*)d_in[7];
    const float* Wk     = (const float*)d_in[8];
    const float* bk     = (const float*)d_in[9];
    const float* Wv     = (const float*)d_in[10];
    const float* bv     = (const float*)d_in[11];
    const float* Wo     = (const float*)d_in[12];
    const float* bo     = (const float*)d_in[13];
    const float* W1     = (const float*)d_in[14];
    const float* b1     = (const float*)d_in[15];
    const float* W2     = (const float*)d_in[16];
    const float* b2     = (const float*)d_in[17];
    const float* lnf_w  = (const float*)d_in[18];
    const float* lnf_b  = (const float*)d_in[19];
    float* out = (float*)d_out;

    float *ph, *pln, *pq, *pk, *pv, *pa, *pf;
    cudaGetSymbolAddress((void**)&ph,  g_h);
    cudaGetSymbolAddress((void**)&pln, g_ln);
    cudaGetSymbolAddress((void**)&pq,  g_q);
    cudaGetSymbolAddress((void**)&pk,  g_k);
    cudaGetSymbolAddress((void**)&pv,  g_v);
    cudaGetSymbolAddress((void**)&pa,  g_att);
    cudaGetSymbolAddress((void**)&pf,  g_ff);

    const int attn_smem = (3 * 64 * PADW + 64 * 64) * (int)sizeof(float); // 68608
    cudaFuncSetAttribute(attn_kernel,
                         cudaFuncAttributeMaxDynamicSharedMemorySize, attn_smem);
    cudaFuncSetAttribute(gemm_tc_kernel,
                         cudaFuncAttributeMaxDynamicSharedMemorySize, GEMM_SMEM);
    cudaFuncSetAttribute(gemm_qkv_kernel,
                         cudaFuncAttributeMaxDynamicSharedMemorySize, GEMM_SMEM);

    const size_t SD   = (size_t)T * D;        // per-stack activation stride
    const size_t SF   = (size_t)T * FF;
    const size_t WS   = (size_t)NL * D * D;   // per-stack weight stride
    const size_t W1S  = (size_t)NL * D * FF;
    const size_t BS   = (size_t)NL * D;
    const size_t B1S  = (size_t)NL * FF;

    add_pos_kernel<<<T * D / 4 / 256, 256>>>(x, pos, ph);

    for (int l = 0; l < NL; l++) {
        const size_t wo  = (size_t)l * D * D;
        const size_t w1o = (size_t)l * D * FF;
        const size_t w2o = (size_t)l * FF * D;
        const size_t bo_ = (size_t)l * D;
        const size_t b1o = (size_t)l * FF;

        ln_kernel<<<dim3(T, 2), 128>>>(ph, ln1_w + bo_, (int)BS, ln1_b + bo_, (int)BS, pln);

        gemm_qkv_kernel<<<dim3(D / BN, T / BM, 6), 128, GEMM_SMEM>>>(
            pln, SD, Wq + wo, Wk + wo, Wv + wo, WS,
            bq + bo_, bk + bo_, bv + bo_, BS, pq, pk, pv, SD);

        attn_kernel<<<dim3(T / 64, H, 2), 256, attn_smem>>>(pq, pk, pv, pa);

        gemm_tc_kernel<<<dim3(D / BN, T / BM, 2), 128, GEMM_SMEM>>>(
            pa, SD, Wo + wo, WS, bo + bo_, BS, ph, SD, ph, SD, D, D, 0);

        ln_kernel<<<dim3(T, 2), 128>>>(ph, ln2_w + bo_, (int)BS, ln2_b + bo_, (int)BS, pln);

        gemm_tc_kernel<<<dim3(FF / BN, T / BM, 2), 128, GEMM_SMEM>>>(
            pln, SD, W1 + w1o, W1S, b1 + b1o, B1S, nullptr, 0, pf, SF, FF, D, 1);
        gemm_tc_kernel<<<dim3(D / BN, T / BM, 2), 128, GEMM_SMEM>>>(
            pf, SF, W2 + w2o, W1S, b2 + bo_, BS, ph, SD, ph, SD, D, FF, 0);
    }
    // final LN: same weights for both stacks (stride 0); out is [2][T][D]
    ln_kernel<<<dim3(T, 2), 128>>>(ph, lnf_w, 0, lnf_b, 0, out);
}

// round 10
// speedup vs baseline: 1.9571x; 1.1093x over previous
#include <cuda_runtime.h>
#include <cstdint>
#include <cstddef>
#include <mma.h>
#include <math.h>

using namespace nvcuda;

#define T 2048
#define D 512
#define H 8
#define DH 64
#define NL 2
#define FF 1024

// ---------------- scratch (per-stack: 2x) -----------------------------------
__device__ float g_h  [2 * T * D];
__device__ float g_ln [2 * T * D];
__device__ float g_q  [2 * T * D];
__device__ float g_k  [2 * T * D];
__device__ float g_v  [2 * T * D];
__device__ float g_att[2 * T * D];
__device__ float g_ff [2 * T * FF];

// ---------------- cp.async helpers -------------------------------------------
__device__ __forceinline__ void cp_async16(unsigned smem, const void* gmem) {
    asm volatile("cp.async.cg.shared.global [%0], [%1], 16;\n" :: "r"(smem), "l"(gmem));
}
__device__ __forceinline__ void cp_commit() {
    asm volatile("cp.async.commit_group;\n");
}
template<int N>
__device__ __forceinline__ void cp_wait() {
    asm volatile("cp.async.wait_group %0;\n" :: "n"(N));
}

// ---------------- x + pos -> both stacks -------------------------------------
__global__ void add_pos_kernel(const float* __restrict__ x,
                               const float* __restrict__ pos,
                               float* __restrict__ out) {
    int i = blockIdx.x * blockDim.x + threadIdx.x;   // float4 index
    float4 a = ((const float4*)x)[i];
    float4 b = ((const float4*)pos)[i];
    a.x += b.x; a.y += b.y; a.z += b.z; a.w += b.w;
    ((float4*)out)[i] = a;
    ((float4*)(out + T * D))[i] = a;
}

// ---------------- batched LayerNorm (grid.y = stack) -------------------------
__global__ void ln_kernel(const float* __restrict__ x,
                          const float* __restrict__ w, int ws,
                          const float* __restrict__ b, int bs,
                          float* __restrict__ out) {
    int s = blockIdx.y;
    int row = blockIdx.x;
    int t = threadIdx.x;  // 128 threads, 4 floats each
    const float* xr = x + (size_t)s * T * D + row * D;
    const float* wp = w + (size_t)s * ws;
    const float* bp = b + (size_t)s * bs;
    float4 v = *(const float4*)(xr + t * 4);
    float sm_ = v.x + v.y + v.z + v.w;
    float ss = v.x * v.x + v.y * v.y + v.z * v.z + v.w * v.w;
    #pragma unroll
    for (int o = 16; o > 0; o >>= 1) {
        sm_ += __shfl_xor_sync(0xffffffffu, sm_, o);
        ss  += __shfl_xor_sync(0xffffffffu, ss, o);
    }
    __shared__ float sh[8];
    int wid = t >> 5, lane = t & 31;
    if (lane == 0) { sh[wid] = sm_; sh[4 + wid] = ss; }
    __syncthreads();
    float S  = sh[0] + sh[1] + sh[2] + sh[3];
    float SS = sh[4] + sh[5] + sh[6] + sh[7];
    float mu = S * (1.0f / D);
    float var = SS * (1.0f / D) - mu * mu;
    float rstd = rsqrtf(var + 1e-5f);
    float4 wv = *(const float4*)(wp + t * 4);
    float4 bv = *(const float4*)(bp + t * 4);
    float4 r;
    r.x = (v.x - mu) * rstd * wv.x + bv.x;
    r.y = (v.y - mu) * rstd * wv.y + bv.y;
    r.z = (v.z - mu) * rstd * wv.z + bv.z;
    r.w = (v.w - mu) * rstd * wv.w + bv.w;
    *(float4*)(out + (size_t)s * T * D + row * D + t * 4) = r;
}

// ---------------- TF32 tensor-core GEMM core ---------------------------------
// Block tile 128x64, BK=32, 128 threads (4 warps, 2x2), warp tile 64x32.
// 3-stage cp.async pipeline, dynamic smem.
#define BM 128
#define BN 64
#define BK 32
#define APAD 36
#define BPAD 68
#define NSTG 3
#define STAGE_F (BM * APAD + BK * BPAD)   // 6784 floats / stage
#define GEMM_SMEM (NSTG * STAGE_F * 4)    // 81408 bytes

__device__ __forceinline__ void gemm_body(
    const float* __restrict__ A, const float* __restrict__ W,
    const float* __restrict__ bias, const float* __restrict__ res,
    float* __restrict__ C, int N, int K, int act,
    int m0, int n0, float* sm)
{
    const int t = threadIdx.x;
    const int wid = t >> 5;
    const int wm0 = (wid & 1) * 64;
    const int wn0 = (wid >> 1) * 32;
    const unsigned smem_base = (unsigned)__cvta_generic_to_shared(sm);
    const int NITER = K / BK;

    auto load_stage = [&](int stg, int iter) {
        unsigned base = smem_base + stg * STAGE_F * 4;
        int k0 = iter * BK;
        #pragma unroll
        for (int i = 0; i < 8; i++) {        // A: 128x32, 8 chunks/row
            int c = t + i * 128;
            int rowa = c >> 3, cola = (c & 7) * 4;
            cp_async16(base + (rowa * APAD + cola) * 4,
                       A + (size_t)(m0 + rowa) * K + k0 + cola);
        }
        unsigned bbase = base + BM * APAD * 4;
        #pragma unroll
        for (int i = 0; i < 4; i++) {        // B: 32x64, 16 chunks/row
            int c = t + i * 128;
            int rowb = c >> 4, colb = (c & 15) * 4;
            cp_async16(bbase + (rowb * BPAD + colb) * 4,
                       W + (size_t)(k0 + rowb) * N + n0 + colb);
        }
    };

    wmma::fragment<wmma::accumulator, 16, 16, 8, float> acc[4][2];
    #pragma unroll
    for (int i = 0; i < 4; i++)
        #pragma unroll
        for (int j = 0; j < 2; j++)
            wmma::fill_fragment(acc[i][j], 0.0f);

    #pragma unroll
    for (int p = 0; p < NSTG - 1; p++) { load_stage(p, p); cp_commit(); }

    for (int it = 0; it < NITER; it++) {
        cp_wait<NSTG - 2>();
        __syncthreads();
        if (it + NSTG - 1 < NITER) load_stage((it + NSTG - 1) % NSTG, it + NSTG - 1);
        cp_commit();

        const float* As = sm + (it % NSTG) * STAGE_F;
        const float* Bs = As + BM * APAD;
        #pragma unroll
        for (int kk = 0; kk < BK; kk += 8) {
            wmma::fragment<wmma::matrix_a, 16, 16, 8, wmma::precision::tf32, wmma::row_major> af[4];
            wmma::fragment<wmma::matrix_b, 16, 16, 8, wmma::precision::tf32, wmma::row_major> bf[2];
            #pragma unroll
            for (int i = 0; i < 4; i++)
                wmma::load_matrix_sync(af[i], As + (wm0 + 16 * i) * APAD + kk, APAD);
            #pragma unroll
            for (int j = 0; j < 2; j++)
                wmma::load_matrix_sync(bf[j], Bs + kk * BPAD + wn0 + 16 * j, BPAD);
            #pragma unroll
            for (int i = 0; i < 4; i++)
                #pragma unroll
                for (int j = 0; j < 2; j++)
                    wmma::mma_sync(acc[i][j], af[i], bf[j], acc[i][j]);
        }
    }

    // epilogue: accs -> smem -> global with bias/act/residual
    __syncthreads();
    #pragma unroll
    for (int i = 0; i < 4; i++)
        #pragma unroll
        for (int j = 0; j < 2; j++)
            wmma::store_matrix_sync(sm + (wm0 + 16 * i) * BPAD + wn0 + 16 * j,
                                    acc[i][j], BPAD, wmma::mem_row_major);
    __syncthreads();

    const int cr = t >> 4, cc = (t & 15) * 4;  // 8 rows/pass, 16 passes
    float4 bb = *(const float4*)(bias + n0 + cc);
    #pragma unroll
    for (int i = 0; i < 16; i++) {
        int r = cr + 8 * i;
        int m = m0 + r;
        float4 v = *(const float4*)(sm + r * BPAD + cc);
        v.x += bb.x; v.y += bb.y; v.z += bb.z; v.w += bb.w;
        if (act == 1) {
            v.x = 0.5f * v.x * (1.0f + erff(v.x * 0.70710678118654752f));
            v.y = 0.5f * v.y * (1.0f + erff(v.y * 0.70710678118654752f));
            v.z = 0.5f * v.z * (1.0f + erff(v.z * 0.70710678118654752f));
            v.w = 0.5f * v.w * (1.0f + erff(v.w * 0.70710678118654752f));
        }
        if (res) {
            float4 rv = *(const float4*)(res + (size_t)m * N + n0 + cc);
            v.x += rv.x; v.y += rv.y; v.z += rv.z; v.w += rv.w;
        }
        *(float4*)(C + (size_t)m * N + n0 + cc) = v;
    }
}

// generic GEMM: blockIdx.z = stack
__global__ __launch_bounds__(128)
void gemm_tc_kernel(const float* __restrict__ A,  size_t aS,
                    const float* __restrict__ W,  size_t wS,
                    const float* __restrict__ bias, size_t biasS,
                    const float* __restrict__ res,  size_t resS,
                    float* __restrict__ C, size_t cS,
                    int N, int K, int act) {
    extern __shared__ float sm[];
    const int s = blockIdx.z;
    gemm_body(A + s * aS, W + s * wS, bias + s * biasS,
              res ? res + s * resS : nullptr, C + s * cS,
              N, K, act,
              blockIdx.y * BM, blockIdx.x * BN, sm);
}

// fused QKV: blockIdx.z in 0..5 -> (which = z>>1, stack = z&1)
__global__ __launch_bounds__(128)
void gemm_qkv_kernel(const float* __restrict__ A,  size_t aS,
                     const float* __restrict__ W0,
                     const float* __restrict__ W1_,
                     const float* __restrict__ W2_, size_t wS,
                     const float* __restrict__ b0,
                     const float* __restrict__ b1_,
                     const float* __restrict__ b2_, size_t biasS,
                     float* __restrict__ C0,
                     float* __restrict__ C1,
                     float* __restrict__ C2, size_t cS) {
    extern __shared__ float sm[];
    const int z = blockIdx.z;
    const int which = z >> 1, s = z & 1;
    const float* W = (which == 0) ? W0 : (which == 1) ? W1_ : W2_;
    const float* bia = (which == 0) ? b0 : (which == 1) ? b1_ : b2_;
    float* C = (which == 0) ? C0 : (which == 1) ? C1 : C2;
    gemm_body(A + s * aS, W + s * wS, bia + s * biasS, nullptr, C + s * cS,
              D, D, 0,
              blockIdx.y * BM, blockIdx.x * BN, sm);
}

// ---------------- TF32 tensor-core flash attention ---------------------------
// grid (T/64, H, 2), 128 threads (4 warps). BQ=BK=64, Dh=64.
// Warp w owns the 16-row query strip [16w,16w+16); softmax / P / PV / O-update
// are warp-local, so only 2 __syncthreads per key tile (around K/V load).
#define AP 72
#define ATTN_SMEM (5 * 64 * AP * 4)   // Qs,Ks,Vs,Ss,Ds = 92160 bytes

__global__ __launch_bounds__(128)
void attn_tc_kernel(const float* __restrict__ q,
                    const float* __restrict__ k,
                    const float* __restrict__ v,
                    float* __restrict__ out) {
    extern __shared__ float smdyn[];
    float* Qs = smdyn;                // [64][AP] (q, d), pre-scaled
    float* Ks = smdyn + 64 * AP;      // [64][AP] (k, d)
    float* Vs = smdyn + 2 * 64 * AP;  // [64][AP] (k, d)
    float* Ss = smdyn + 3 * 64 * AP;  // [64][AP] scores then P
    float* Ds = smdyn + 4 * 64 * AP;  // [64][AP] PV delta

    const int t = threadIdx.x;
    const int w = t >> 5;
    const int q0 = blockIdx.x * 64;
    const int head = blockIdx.y;
    const int stk = blockIdx.z;
    const int bw = stk == 0 ? 999 : 9;
    const size_t sb = (size_t)stk * T * D;
    const float* qh = q + sb + head * DH;
    const float* kh = k + sb + head * DH;
    const float* vh = v + sb + head * DH;

    // load Q tile, pre-scaled by 1/sqrt(Dh)
    #pragma unroll
    for (int i = 0; i < 8; i++) {
        int c = t + i * 128;              // 1024 float4 chunks
        int row = c >> 4, col = (c & 15) * 4;
        float4 qv = *(const float4*)(qh + (size_t)(q0 + row) * D + col);
        qv.x *= 0.125f; qv.y *= 0.125f; qv.z *= 0.125f; qv.w *= 0.125f;
        *(float4*)(Qs + row * AP + col) = qv;
    }

    // softmax/O ownership: 2 threads per row (shfl-pair on bit 0)
    const int row = t >> 1, half = t & 1;
    const int qi = q0 + row;
    float o[32];
    #pragma unroll
    for (int c = 0; c < 32; c++) o[c] = 0.f;
    float mrow = -1e30f, lrow = 0.f;

    const int kt0 = max(0, q0 - bw) >> 6;
    const int kt1 = q0 >> 6;
    for (int kt = kt0; kt <= kt1; kt++) {
        const int j0 = kt << 6;
        __syncthreads();   // previous tile's Ks/Vs readers done
        #pragma unroll
        for (int i = 0; i < 8; i++) {
            int c = t + i * 128;
            int r = c >> 4, col = (c & 15) * 4;
            *(float4*)(Ks + r * AP + col) =
                *(const float4*)(kh + (size_t)(j0 + r) * D + col);
            *(float4*)(Vs + r * AP + col) =
                *(const float4*)(vh + (size_t)(j0 + r) * D + col);
        }
        __syncthreads();

        // S strip = Q[16w..16w+16) @ K^T  (wmma, K^T via col_major over Ks)
        {
            wmma::fragment<wmma::accumulator, 16, 16, 8, float> sacc[4];
            #pragma unroll
            for (int j = 0; j < 4; j++) wmma::fill_fragment(sacc[j], 0.0f);
            #pragma unroll
            for (int kk = 0; kk < 64; kk += 8) {
                wmma::fragment<wmma::matrix_a, 16, 16, 8, wmma::precision::tf32, wmma::row_major> af;
                wmma::load_matrix_sync(af, Qs + (16 * w) * AP + kk, AP);
                #pragma unroll
                for (int j = 0; j < 4; j++) {
                    wmma::fragment<wmma::matrix_b, 16, 16, 8, wmma::precision::tf32, wmma::col_major> bf;
                    wmma::load_matrix_sync(bf, Ks + (16 * j) * AP + kk, AP);
                    wmma::mma_sync(sacc[j], af, bf, sacc[j]);
                }
            }
            #pragma unroll
            for (int j = 0; j < 4; j++)
                wmma::store_matrix_sync(Ss + (16 * w) * AP + 16 * j, sacc[j],
                                        AP, wmma::mem_row_major);
        }
        // warp-local from here on (strip rows == warp's own rows)

        // online softmax: 2 threads/row, 32 cols each
        {
            float sv[32];
            float* srow = Ss + row * AP + half * 32;
            #pragma unroll
            for (int c = 0; c < 32; c++) {
                float x = srow[c];
                int kj = j0 + half * 32 + c;
                if (kj > qi || kj < qi - bw) x = -1e30f;
                sv[c] = x;
            }
            float mx = -1e30f;
            #pragma unroll
            for (int c = 0; c < 32; c++) mx = fmaxf(mx, sv[c]);
            mx = fmaxf(mx, __shfl_xor_sync(0xffffffffu, mx, 1));
            float mn = fmaxf(mrow, mx);
            float alpha = __expf(mrow - mn);
            float rs = 0.f;
            #pragma unroll
            for (int c = 0; c < 32; c++) {
                float p = (sv[c] < -1e29f) ? 0.f : __expf(sv[c] - mn);
                sv[c] = p;
                rs += p;
            }
            rs += __shfl_xor_sync(0xffffffffu, rs, 1);
            mrow = mn;
            lrow = lrow * alpha + rs;
            #pragma unroll
            for (int c = 0; c < 32; c++) srow[c] = sv[c];
            // O rescale now; delta added after PV
            #pragma unroll
            for (int c = 0; c < 32; c++) o[c] *= alpha;
        }
        __syncwarp();

        // PV strip = P[16w..16w+16) @ V  (wmma row-major)
        {
            wmma::fragment<wmma::accumulator, 16, 16, 8, float> pacc[4];
            #pragma unroll
            for (int j = 0; j < 4; j++) wmma::fill_fragment(pacc[j], 0.0f);
            #pragma unroll
            for (int kk = 0; kk < 64; kk += 8) {
                wmma::fragment<wmma::matrix_a, 16, 16, 8, wmma::precision::tf32, wmma::row_major> af;
                wmma::load_matrix_sync(af, Ss + (16 * w) * AP + kk, AP);
                #pragma unroll
                for (int j = 0; j < 4; j++) {
                    wmma::fragment<wmma::matrix_b, 16, 16, 8, wmma::precision::tf32, wmma::row_major> bf;
                    wmma::load_matrix_sync(bf, Vs + kk * AP + 16 * j, AP);
                    wmma::mma_sync(pacc[j], af, bf, pacc[j]);
                }
            }
            #pragma unroll
            for (int j = 0; j < 4; j++)
                wmma::store_matrix_sync(Ds + (16 * w) * AP + 16 * j, pacc[j],
                                        AP, wmma::mem_row_major);
        }
        __syncwarp();

        // O += delta (warp-local read of own strip)
        {
            const float* drow = Ds + row * AP + half * 32;
            #pragma unroll
            for (int c = 0; c < 32; c++) o[c] += drow[c];
        }
    }

    // normalize + write
    const float inv = 1.0f / lrow;
    float* orow = out + sb + (size_t)qi * D + head * DH + half * 32;
    #pragma unroll
    for (int c = 0; c < 32; c += 4) {
        float4 r = {o[c] * inv, o[c + 1] * inv, o[c + 2] * inv, o[c + 3] * inv};
        *(float4*)(orow + c) = r;
    }
}

// ---------------- host orchestration ----------------------------------------
extern "C" void kernel_launch(void* const* d_in, const int* in_sizes, int n_in,
                              void* d_out, int out_size) {
    const float* x      = (const float*)d_in[0];
    const float* pos    = (const float*)d_in[1];
    const float* ln1_w  = (const float*)d_in[2];
    const float* ln1_b  = (const float*)d_in[3];
    const float* ln2_w  = (const float*)d_in[4];
    const float* ln2_b  = (const float*)d_in[5];
    const float* Wq     = (const float*)d_in[6];
    const float* bq     = (const float*)d_in[7];
    const float* Wk     = (const float*)d_in[8];
    const float* bk     = (const float*)d_in[9];
    const float* Wv     = (const float*)d_in[10];
    const float* bv     = (const float*)d_in[11];
    const float* Wo     = (const float*)d_in[12];
    const float* bo     = (const float*)d_in[13];
    const float* W1     = (const float*)d_in[14];
    const float* b1     = (const float*)d_in[15];
    const float* W2     = (const float*)d_in[16];
    const float* b2     = (const float*)d_in[17];
    const float* lnf_w  = (const float*)d_in[18];
    const float* lnf_b  = (const float*)d_in[19];
    float* out = (float*)d_out;

    float *ph, *pln, *pq, *pk, *pv, *pa, *pf;
    cudaGetSymbolAddress((void**)&ph,  g_h);
    cudaGetSymbolAddress((void**)&pln, g_ln);
    cudaGetSymbolAddress((void**)&pq,  g_q);
    cudaGetSymbolAddress((void**)&pk,  g_k);
    cudaGetSymbolAddress((void**)&pv,  g_v);
    cudaGetSymbolAddress((void**)&pa,  g_att);
    cudaGetSymbolAddress((void**)&pf,  g_ff);

    cudaFuncSetAttribute(attn_tc_kernel,
                         cudaFuncAttributeMaxDynamicSharedMemorySize, ATTN_SMEM);
    cudaFuncSetAttribute(gemm_tc_kernel,
                         cudaFuncAttributeMaxDynamicSharedMemorySize, GEMM_SMEM);
    cudaFuncSetAttribute(gemm_qkv_kernel,
                         cudaFuncAttributeMaxDynamicSharedMemorySize, GEMM_SMEM);

    const size_t SD   = (size_t)T * D;        // per-stack activation stride
    const size_t SF   = (size_t)T * FF;
    const size_t WS   = (size_t)NL * D * D;   // per-stack weight stride
    const size_t W1S  = (size_t)NL * D * FF;
    const size_t BS   = (size_t)NL * D;
    const size_t B1S  = (size_t)NL * FF;

    add_pos_kernel<<<T * D / 4 / 256, 256>>>(x, pos, ph);

    for (int l = 0; l < NL; l++) {
        const size_t wo  = (size_t)l * D * D;
        const size_t w1o = (size_t)l * D * FF;
        const size_t w2o = (size_t)l * FF * D;
        const size_t bo_ = (size_t)l * D;
        const size_t b1o = (size_t)l * FF;

        ln_kernel<<<dim3(T, 2), 128>>>(ph, ln1_w + bo_, (int)BS, ln1_b + bo_, (int)BS, pln);

        gemm_qkv_kernel<<<dim3(D / BN, T / BM, 6), 128, GEMM_SMEM>>>(
            pln, SD, Wq + wo, Wk + wo, Wv + wo, WS,
            bq + bo_, bk + bo_, bv + bo_, BS, pq, pk, pv, SD);

        attn_tc_kernel<<<dim3(T / 64, H, 2), 128, ATTN_SMEM>>>(pq, pk, pv, pa);

        gemm_tc_kernel<<<dim3(D / BN, T / BM, 2), 128, GEMM_SMEM>>>(
            pa, SD, Wo + wo, WS, bo + bo_, BS, ph, SD, ph, SD, D, D, 0);

        ln_kernel<<<dim3(T, 2), 128>>>(ph, ln2_w + bo_, (int)BS, ln2_b + bo_, (int)BS, pln);

        gemm_tc_kernel<<<dim3(FF / BN, T / BM, 2), 128, GEMM_SMEM>>>(
            pln, SD, W1 + w1o, W1S, b1 + b1o, B1S, nullptr, 0, pf, SF, FF, D, 1);
        gemm_tc_kernel<<<dim3(D / BN, T / BM, 2), 128, GEMM_SMEM>>>(
            pf, SF, W2 + w2o, W1S, b2 + bo_, BS, ph, SD, ph, SD, D, FF, 0);
    }
    // final LN: same weights for both stacks (stride 0); out is [2][T][D]
    ln_kernel<<<dim3(T, 2), 128>>>(ph, lnf_w, 0, lnf_b, 0, out);
}

// round 14
// speedup vs baseline: 1.9680x; 1.0056x over previous
#include <cuda_runtime.h>
#include <cstdint>
#include <cstddef>
#include <mma.h>
#include <math.h>

using namespace nvcuda;

#define T 2048
#define D 512
#define H 8
#define DH 64
#define NL 2
#define FF 1024

// ---------------- scratch (per-stack: 2x) -----------------------------------
__device__ float g_h  [2 * T * D];
__device__ float g_ln [2 * T * D];
__device__ float g_q  [2 * T * D];
__device__ float g_k  [2 * T * D];
__device__ float g_v  [2 * T * D];
__device__ float g_att[2 * T * D];
__device__ float g_ff [2 * T * FF];

// ---------------- cp.async helpers -------------------------------------------
__device__ __forceinline__ void cp_async16(unsigned smem, const void* gmem) {
    asm volatile("cp.async.cg.shared.global [%0], [%1], 16;\n" :: "r"(smem), "l"(gmem));
}
__device__ __forceinline__ void cp_commit() {
    asm volatile("cp.async.commit_group;\n");
}
template<int N>
__device__ __forceinline__ void cp_wait() {
    asm volatile("cp.async.wait_group %0;\n" :: "n"(N));
}

// ---------------- x + pos -> both stacks -------------------------------------
__global__ void add_pos_kernel(const float* __restrict__ x,
                               const float* __restrict__ pos,
                               float* __restrict__ out) {
    int i = blockIdx.x * blockDim.x + threadIdx.x;   // float4 index
    float4 a = ((const float4*)x)[i];
    float4 b = ((const float4*)pos)[i];
    a.x += b.x; a.y += b.y; a.z += b.z; a.w += b.w;
    ((float4*)out)[i] = a;
    ((float4*)(out + T * D))[i] = a;
}

// ---------------- batched LayerNorm (grid.y = stack) -------------------------
__global__ void ln_kernel(const float* __restrict__ x,
                          const float* __restrict__ w, int ws,
                          const float* __restrict__ b, int bs,
                          float* __restrict__ out) {
    int s = blockIdx.y;
    int row = blockIdx.x;
    int t = threadIdx.x;  // 128 threads, 4 floats each
    const float* xr = x + (size_t)s * T * D + row * D;
    const float* wp = w + (size_t)s * ws;
    const float* bp = b + (size_t)s * bs;
    float4 v = *(const float4*)(xr + t * 4);
    float sm_ = v.x + v.y + v.z + v.w;
    float ss = v.x * v.x + v.y * v.y + v.z * v.z + v.w * v.w;
    #pragma unroll
    for (int o = 16; o > 0; o >>= 1) {
        sm_ += __shfl_xor_sync(0xffffffffu, sm_, o);
        ss  += __shfl_xor_sync(0xffffffffu, ss, o);
    }
    __shared__ float sh[8];
    int wid = t >> 5, lane = t & 31;
    if (lane == 0) { sh[wid] = sm_; sh[4 + wid] = ss; }
    __syncthreads();
    float S  = sh[0] + sh[1] + sh[2] + sh[3];
    float SS = sh[4] + sh[5] + sh[6] + sh[7];
    float mu = S * (1.0f / D);
    float var = SS * (1.0f / D) - mu * mu;
    float rstd = rsqrtf(var + 1e-5f);
    float4 wv = *(const float4*)(wp + t * 4);
    float4 bv = *(const float4*)(bp + t * 4);
    float4 r;
    r.x = (v.x - mu) * rstd * wv.x + bv.x;
    r.y = (v.y - mu) * rstd * wv.y + bv.y;
    r.z = (v.z - mu) * rstd * wv.z + bv.z;
    r.w = (v.w - mu) * rstd * wv.w + bv.w;
    *(float4*)(out + (size_t)s * T * D + row * D + t * 4) = r;
}

// ---------------- TF32 tensor-core GEMM core ---------------------------------
// Block tile 128x64, BK=32, 128 threads (4 warps, 2x2), warp tile 64x32.
// 3-stage cp.async pipeline, dynamic smem.
#define BM 128
#define BN 64
#define BK 32
#define APAD 36
#define BPAD 68
#define NSTG 3
#define STAGE_F (BM * APAD + BK * BPAD)   // 6784 floats / stage
#define GEMM_SMEM (NSTG * STAGE_F * 4)    // 81408 bytes

__device__ __forceinline__ void gemm_body(
    const float* __restrict__ A, const float* __restrict__ W,
    const float* __restrict__ bias, const float* __restrict__ res,
    float* __restrict__ C, int N, int K, int act,
    int m0, int n0, float* sm)
{
    const int t = threadIdx.x;
    const int wid = t >> 5;
    const int wm0 = (wid & 1) * 64;
    const int wn0 = (wid >> 1) * 32;
    const unsigned smem_base = (unsigned)__cvta_generic_to_shared(sm);
    const int NITER = K / BK;

    auto load_stage = [&](int stg, int iter) {
        unsigned base = smem_base + stg * STAGE_F * 4;
        int k0 = iter * BK;
        #pragma unroll
        for (int i = 0; i < 8; i++) {        // A: 128x32, 8 chunks/row
            int c = t + i * 128;
            int rowa = c >> 3, cola = (c & 7) * 4;
            cp_async16(base + (rowa * APAD + cola) * 4,
                       A + (size_t)(m0 + rowa) * K + k0 + cola);
        }
        unsigned bbase = base + BM * APAD * 4;
        #pragma unroll
        for (int i = 0; i < 4; i++) {        // B: 32x64, 16 chunks/row
            int c = t + i * 128;
            int rowb = c >> 4, colb = (c & 15) * 4;
            cp_async16(bbase + (rowb * BPAD + colb) * 4,
                       W + (size_t)(k0 + rowb) * N + n0 + colb);
        }
    };

    wmma::fragment<wmma::accumulator, 16, 16, 8, float> acc[4][2];
    #pragma unroll
    for (int i = 0; i < 4; i++)
        #pragma unroll
        for (int j = 0; j < 2; j++)
            wmma::fill_fragment(acc[i][j], 0.0f);

    #pragma unroll
    for (int p = 0; p < NSTG - 1; p++) { load_stage(p, p); cp_commit(); }

    for (int it = 0; it < NITER; it++) {
        cp_wait<NSTG - 2>();
        __syncthreads();
        if (it + NSTG - 1 < NITER) load_stage((it + NSTG - 1) % NSTG, it + NSTG - 1);
        cp_commit();

        const float* As = sm + (it % NSTG) * STAGE_F;
        const float* Bs = As + BM * APAD;
        #pragma unroll
        for (int kk = 0; kk < BK; kk += 8) {
            wmma::fragment<wmma::matrix_a, 16, 16, 8, wmma::precision::tf32, wmma::row_major> af[4];
            wmma::fragment<wmma::matrix_b, 16, 16, 8, wmma::precision::tf32, wmma::row_major> bf[2];
            #pragma unroll
            for (int i = 0; i < 4; i++)
                wmma::load_matrix_sync(af[i], As + (wm0 + 16 * i) * APAD + kk, APAD);
            #pragma unroll
            for (int j = 0; j < 2; j++)
                wmma::load_matrix_sync(bf[j], Bs + kk * BPAD + wn0 + 16 * j, BPAD);
            #pragma unroll
            for (int i = 0; i < 4; i++)
                #pragma unroll
                for (int j = 0; j < 2; j++)
                    wmma::mma_sync(acc[i][j], af[i], bf[j], acc[i][j]);
        }
    }

    // epilogue: accs -> smem -> global with bias/act/residual
    __syncthreads();
    #pragma unroll
    for (int i = 0; i < 4; i++)
        #pragma unroll
        for (int j = 0; j < 2; j++)
            wmma::store_matrix_sync(sm + (wm0 + 16 * i) * BPAD + wn0 + 16 * j,
                                    acc[i][j], BPAD, wmma::mem_row_major);
    __syncthreads();

    const int cr = t >> 4, cc = (t & 15) * 4;  // 8 rows/pass, 16 passes
    float4 bb = *(const float4*)(bias + n0 + cc);
    #pragma unroll
    for (int i = 0; i < 16; i++) {
        int r = cr + 8 * i;
        int m = m0 + r;
        float4 v = *(const float4*)(sm + r * BPAD + cc);
        v.x += bb.x; v.y += bb.y; v.z += bb.z; v.w += bb.w;
        if (act == 1) {
            v.x = 0.5f * v.x * (1.0f + erff(v.x * 0.70710678118654752f));
            v.y = 0.5f * v.y * (1.0f + erff(v.y * 0.70710678118654752f));
            v.z = 0.5f * v.z * (1.0f + erff(v.z * 0.70710678118654752f));
            v.w = 0.5f * v.w * (1.0f + erff(v.w * 0.70710678118654752f));
        }
        if (res) {
            float4 rv = *(const float4*)(res + (size_t)m * N + n0 + cc);
            v.x += rv.x; v.y += rv.y; v.z += rv.z; v.w += rv.w;
        }
        *(float4*)(C + (size_t)m * N + n0 + cc) = v;
    }
}

// generic GEMM: blockIdx.z = stack
__global__ __launch_bounds__(128)
void gemm_tc_kernel(const float* __restrict__ A,  size_t aS,
                    const float* __restrict__ W,  size_t wS,
                    const float* __restrict__ bias, size_t biasS,
                    const float* __restrict__ res,  size_t resS,
                    float* __restrict__ C, size_t cS,
                    int N, int K, int act) {
    extern __shared__ float sm[];
    const int s = blockIdx.z;
    gemm_body(A + s * aS, W + s * wS, bias + s * biasS,
              res ? res + s * resS : nullptr, C + s * cS,
              N, K, act,
              blockIdx.y * BM, blockIdx.x * BN, sm);
}

// fused QKV: blockIdx.z in 0..5 -> (which = z>>1, stack = z&1)
__global__ __launch_bounds__(128)
void gemm_qkv_kernel(const float* __restrict__ A,  size_t aS,
                     const float* __restrict__ W0,
                     const float* __restrict__ W1_,
                     const float* __restrict__ W2_, size_t wS,
                     const float* __restrict__ b0,
                     const float* __restrict__ b1_,
                     const float* __restrict__ b2_, size_t biasS,
                     float* __restrict__ C0,
                     float* __restrict__ C1,
                     float* __restrict__ C2, size_t cS) {
    extern __shared__ float sm[];
    const int z = blockIdx.z;
    const int which = z >> 1, s = z & 1;
    const float* W = (which == 0) ? W0 : (which == 1) ? W1_ : W2_;
    const float* bia = (which == 0) ? b0 : (which == 1) ? b1_ : b2_;
    float* C = (which == 0) ? C0 : (which == 1) ? C1 : C2;
    gemm_body(A + s * aS, W + s * wS, bia + s * biasS, nullptr, C + s * cS,
              D, D, 0,
              blockIdx.y * BM, blockIdx.x * BN, sm);
}

// ---------------- TF32 tensor-core flash attention ---------------------------
// grid (T/128, H, 2), 256 threads (8 warps). BQ=128, BKT=64, Dh=64.
// Warp w owns the 16-row query strip; softmax / P / PV / O-update warp-local.
// K/V tiles double-buffered via cp.async (prefetch next tile during compute).
#define AP 72
#define AQ_F   (128 * AP)            // Qs floats
#define AKV_F  (64 * AP)             // one K or V buffer
#define ATTN_SMEM ((AQ_F + 4 * AKV_F + 128 * AP) * 4)   // 147456 bytes

__global__ __launch_bounds__(256)
void attn_tc_kernel(const float* __restrict__ q,
                    const float* __restrict__ k,
                    const float* __restrict__ v,
                    float* __restrict__ out) {
    extern __shared__ float smdyn[];
    float* Qs = smdyn;                         // [128][AP] pre-scaled
    float* Kb = smdyn + AQ_F;                  // [2][64][AP]
    float* Vb = smdyn + AQ_F + 2 * AKV_F;      // [2][64][AP]
    float* Ss = smdyn + AQ_F + 4 * AKV_F;      // [128][AP] S -> P -> PV delta

    const int t = threadIdx.x;
    const int w = t >> 5;
    const int q0 = blockIdx.x * 128;
    const int head = blockIdx.y;
    const int stk = blockIdx.z;
    const int bw = stk == 0 ? 999 : 9;
    const size_t sb = (size_t)stk * T * D;
    const float* qh = q + sb + head * DH;
    const float* kh = k + sb + head * DH;
    const float* vh = v + sb + head * DH;
    const unsigned kb_base = (unsigned)__cvta_generic_to_shared(Kb);
    const unsigned vb_base = (unsigned)__cvta_generic_to_shared(Vb);

    // load Q tile (128x64), pre-scaled by 1/sqrt(Dh)
    #pragma unroll
    for (int i = 0; i < 8; i++) {
        int c = t + i * 256;                   // 2048 float4 chunks
        int row = c >> 4, col = (c & 15) * 4;
        float4 qv = *(const float4*)(qh + (size_t)(q0 + row) * D + col);
        qv.x *= 0.125f; qv.y *= 0.125f; qv.z *= 0.125f; qv.w *= 0.125f;
        *(float4*)(Qs + row * AP + col) = qv;
    }

    // K/V tile async load: 64x64 each -> 1024 chunks; 256 threads -> 4+4 chunks
    auto load_kv = [&](int buf, int j0) {
        unsigned kb = kb_base + buf * AKV_F * 4;
        unsigned vb = vb_base + buf * AKV_F * 4;
        #pragma unroll
        for (int i = 0; i < 4; i++) {
            int c = t + i * 256;
            int r = c >> 4, col = (c & 15) * 4;
            cp_async16(kb + (r * AP + col) * 4, kh + (size_t)(j0 + r) * D + col);
            cp_async16(vb + (r * AP + col) * 4, vh + (size_t)(j0 + r) * D + col);
        }
    };

    // softmax/O ownership: 2 threads per row (shfl pair on bit 0)
    const int row = t >> 1, half = t & 1;
    const int qi = q0 + row;
    float o[32];
    #pragma unroll
    for (int c = 0; c < 32; c++) o[c] = 0.f;
    float mrow = -1e30f, lrow = 0.f;

    const int kt0 = max(0, q0 - bw) >> 6;
    const int kt1 = (q0 + 127) >> 6;

    load_kv(0, kt0 << 6); cp_commit();

    for (int kt = kt0; kt <= kt1; kt++) {
        const int j0 = kt << 6;
        const int buf = (kt - kt0) & 1;
        if (kt < kt1) { load_kv(buf ^ 1, (kt + 1) << 6); cp_commit(); cp_wait<1>(); }
        else          { cp_wait<0>(); }
        __syncthreads();   // current K/V visible to all warps

        const float* Ks = Kb + buf * AKV_F;
        const float* Vs = Vb + buf * AKV_F;

        // S strip = Q[16w..16w+16) @ K^T
        {
            wmma::fragment<wmma::accumulator, 16, 16, 8, float> sacc[4];
            #pragma unroll
            for (int j = 0; j < 4; j++) wmma::fill_fragment(sacc[j], 0.0f);
            #pragma unroll
            for (int kk = 0; kk < 64; kk += 8) {
                wmma::fragment<wmma::matrix_a, 16, 16, 8, wmma::precision::tf32, wmma::row_major> af;
                wmma::load_matrix_sync(af, Qs + (16 * w) * AP + kk, AP);
                #pragma unroll
                for (int j = 0; j < 4; j++) {
                    wmma::fragment<wmma::matrix_b, 16, 16, 8, wmma::precision::tf32, wmma::col_major> bf;
                    wmma::load_matrix_sync(bf, Ks + (16 * j) * AP + kk, AP);
                    wmma::mma_sync(sacc[j], af, bf, sacc[j]);
                }
            }
            #pragma unroll
            for (int j = 0; j < 4; j++)
                wmma::store_matrix_sync(Ss + (16 * w) * AP + 16 * j, sacc[j],
                                        AP, wmma::mem_row_major);
        }
        // warp-local: softmax on own strip (2 threads/row, 32 cols each)
        {
            float sv[32];
            float* srow = Ss + row * AP + half * 32;
            #pragma unroll
            for (int c = 0; c < 32; c++) {
                float x = srow[c];
                int kj = j0 + half * 32 + c;
                if (kj > qi || kj < qi - bw) x = -1e30f;
                sv[c] = x;
            }
            float mx = -1e30f;
            #pragma unroll
            for (int c = 0; c < 32; c++) mx = fmaxf(mx, sv[c]);
            mx = fmaxf(mx, __shfl_xor_sync(0xffffffffu, mx, 1));
            float mn = fmaxf(mrow, mx);
            float alpha = __expf(mrow - mn);
            float rs = 0.f;
            #pragma unroll
            for (int c = 0; c < 32; c++) {
                float p = (sv[c] < -1e29f) ? 0.f : __expf(sv[c] - mn);
                sv[c] = p;
                rs += p;
            }
            rs += __shfl_xor_sync(0xffffffffu, rs, 1);
            mrow = mn;
            lrow = lrow * alpha + rs;
            #pragma unroll
            for (int c = 0; c < 32; c++) srow[c] = sv[c];
            #pragma unroll
            for (int c = 0; c < 32; c++) o[c] *= alpha;
        }
        __syncwarp();

        // PV strip = P @ V; store delta back into Ss strip (P dead after mma)
        {
            wmma::fragment<wmma::accumulator, 16, 16, 8, float> pacc[4];
            #pragma unroll
            for (int j = 0; j < 4; j++) wmma::fill_fragment(pacc[j], 0.0f);
            #pragma unroll
            for (int kk = 0; kk < 64; kk += 8) {
                wmma::fragment<wmma::matrix_a, 16, 16, 8, wmma::precision::tf32, wmma::row_major> af;
                wmma::load_matrix_sync(af, Ss + (16 * w) * AP + kk, AP);
                #pragma unroll
                for (int j = 0; j < 4; j++) {
                    wmma::fragment<wmma::matrix_b, 16, 16, 8, wmma::precision::tf32, wmma::row_major> bf;
                    wmma::load_matrix_sync(bf, Vs + kk * AP + 16 * j, AP);
                    wmma::mma_sync(pacc[j], af, bf, pacc[j]);
                }
            }
            #pragma unroll
            for (int j = 0; j < 4; j++)
                wmma::store_matrix_sync(Ss + (16 * w) * AP + 16 * j, pacc[j],
                                        AP, wmma::mem_row_major);
        }
        __syncwarp();

        // O += delta
        {
            const float* drow = Ss + row * AP + half * 32;
            #pragma unroll
            for (int c = 0; c < 32; c++) o[c] += drow[c];
        }
        __syncthreads();   // all warps done with this K/V buffer before reuse
    }

    // normalize + write
    const float inv = 1.0f / lrow;
    float* orow = out + sb + (size_t)qi * D + head * DH + half * 32;
    #pragma unroll
    for (int c = 0; c < 32; c += 4) {
        float4 r = {o[c] * inv, o[c + 1] * inv, o[c + 2] * inv, o[c + 3] * inv};
        *(float4*)(orow + c) = r;
    }
}

// ---------------- host orchestration ----------------------------------------
extern "C" void kernel_launch(void* const* d_in, const int* in_sizes, int n_in,
                              void* d_out, int out_size) {
    const float* x      = (const float*)d_in[0];
    const float* pos    = (const float*)d_in[1];
    const float* ln1_w  = (const float*)d_in[2];
    const float* ln1_b  = (const float*)d_in[3];
    const float* ln2_w  = (const float*)d_in[4];
    const float* ln2_b  = (const float*)d_in[5];
    const float* Wq     = (const float*)d_in[6];
    const float* bq     = (const float*)d_in[7];
    const float* Wk     = (const float*)d_in[8];
    const float* bk     = (const float*)d_in[9];
    const float* Wv     = (const float*)d_in[10];
    const float* bv     = (const float*)d_in[11];
    const float* Wo     = (const float*)d_in[12];
    const float* bo     = (const float*)d_in[13];
    const float* W1     = (const float*)d_in[14];
    const float* b1     = (const float*)d_in[15];
    const float* W2     = (const float*)d_in[16];
    const float* b2     = (const float*)d_in[17];
    const float* lnf_w  = (const float*)d_in[18];
    const float* lnf_b  = (const float*)d_in[19];
    float* out = (float*)d_out;

    float *ph, *pln, *pq, *pk, *pv, *pa, *pf;
    cudaGetSymbolAddress((void**)&ph,  g_h);
    cudaGetSymbolAddress((void**)&pln, g_ln);
    cudaGetSymbolAddress((void**)&pq,  g_q);
    cudaGetSymbolAddress((void**)&pk,  g_k);
    cudaGetSymbolAddress((void**)&pv,  g_v);
    cudaGetSymbolAddress((void**)&pa,  g_att);
    cudaGetSymbolAddress((void**)&pf,  g_ff);

    cudaFuncSetAttribute(attn_tc_kernel,
                         cudaFuncAttributeMaxDynamicSharedMemorySize, ATTN_SMEM);
    cudaFuncSetAttribute(gemm_tc_kernel,
                         cudaFuncAttributeMaxDynamicSharedMemorySize, GEMM_SMEM);
    cudaFuncSetAttribute(gemm_qkv_kernel,
                         cudaFuncAttributeMaxDynamicSharedMemorySize, GEMM_SMEM);

    const size_t SD   = (size_t)T * D;        // per-stack activation stride
    const size_t SF   = (size_t)T * FF;
    const size_t WS   = (size_t)NL * D * D;   // per-stack weight stride
    const size_t W1S  = (size_t)NL * D * FF;
    const size_t BS   = (size_t)NL * D;
    const size_t B1S  = (size_t)NL * FF;

    add_pos_kernel<<<T * D / 4 / 256, 256>>>(x, pos, ph);

    for (int l = 0; l < NL; l++) {
        const size_t wo  = (size_t)l * D * D;
        const size_t w1o = (size_t)l * D * FF;
        const size_t w2o = (size_t)l * FF * D;
        const size_t bo_ = (size_t)l * D;
        const size_t b1o = (size_t)l * FF;

        ln_kernel<<<dim3(T, 2), 128>>>(ph, ln1_w + bo_, (int)BS, ln1_b + bo_, (int)BS, pln);

        gemm_qkv_kernel<<<dim3(D / BN, T / BM, 6), 128, GEMM_SMEM>>>(
            pln, SD, Wq + wo, Wk + wo, Wv + wo, WS,
            bq + bo_, bk + bo_, bv + bo_, BS, pq, pk, pv, SD);

        attn_tc_kernel<<<dim3(T / 128, H, 2), 256, ATTN_SMEM>>>(pq, pk, pv, pa);

        gemm_tc_kernel<<<dim3(D / BN, T / BM, 2), 128, GEMM_SMEM>>>(
            pa, SD, Wo + wo, WS, bo + bo_, BS, ph, SD, ph, SD, D, D, 0);

        ln_kernel<<<dim3(T, 2), 128>>>(ph, ln2_w + bo_, (int)BS, ln2_b + bo_, (int)BS, pln);

        gemm_tc_kernel<<<dim3(FF / BN, T / BM, 2), 128, GEMM_SMEM>>>(
            pln, SD, W1 + w1o, W1S, b1 + b1o, B1S, nullptr, 0, pf, SF, FF, D, 1);
        gemm_tc_kernel<<<dim3(D / BN, T / BM, 2), 128, GEMM_SMEM>>>(
            pf, SF, W2 + w2o, W1S, b2 + bo_, BS, ph, SD, ph, SD, D, FF, 0);
    }
    // final LN: same weights for both stacks (stride 0); out is [2][T][D]
    ln_kernel<<<dim3(T, 2), 128>>>(ph, lnf_w, 0, lnf_b, 0, out);
}

// round 15
// speedup vs baseline: 2.3419x; 1.1900x over previous
#include <cuda_runtime.h>
#include <cstdint>
#include <cstddef>
#include <mma.h>
#include <math.h>

using namespace nvcuda;

#define T 2048
#define D 512
#define H 8
#define DH 64
#define NL 2
#define FF 1024

// ---------------- scratch (per-stack: 2x) -----------------------------------
__device__ float g_h  [2 * T * D];
__device__ float g_ln [2 * T * D];
__device__ float g_q  [2 * T * D];
__device__ float g_k  [2 * T * D];
__device__ float g_v  [2 * T * D];
__device__ float g_att[2 * T * D];
__device__ float g_ff [2 * T * FF];

// ---------------- cp.async helpers -------------------------------------------
__device__ __forceinline__ void cp_async16(unsigned smem, const void* gmem) {
    asm volatile("cp.async.cg.shared.global [%0], [%1], 16;\n" :: "r"(smem), "l"(gmem));
}
__device__ __forceinline__ void cp_commit() {
    asm volatile("cp.async.commit_group;\n");
}
template<int N>
__device__ __forceinline__ void cp_wait() {
    asm volatile("cp.async.wait_group %0;\n" :: "n"(N));
}

// m16n8k8 tf32 mma, in-place accumulate
__device__ __forceinline__ void mma_tf32(float* d, const unsigned* a, const unsigned* b) {
    asm volatile(
        "mma.sync.aligned.m16n8k8.row.col.f32.tf32.tf32.f32 "
        "{%0,%1,%2,%3}, {%4,%5,%6,%7}, {%8,%9}, {%0,%1,%2,%3};\n"
        : "+f"(d[0]), "+f"(d[1]), "+f"(d[2]), "+f"(d[3])
        : "r"(a[0]), "r"(a[1]), "r"(a[2]), "r"(a[3]), "r"(b[0]), "r"(b[1]));
}

// ---------------- x + pos -> both stacks -------------------------------------
__global__ void add_pos_kernel(const float* __restrict__ x,
                               const float* __restrict__ pos,
                               float* __restrict__ out) {
    int i = blockIdx.x * blockDim.x + threadIdx.x;   // float4 index
    float4 a = ((const float4*)x)[i];
    float4 b = ((const float4*)pos)[i];
    a.x += b.x; a.y += b.y; a.z += b.z; a.w += b.w;
    ((float4*)out)[i] = a;
    ((float4*)(out + T * D))[i] = a;
}

// ---------------- batched LayerNorm (grid.y = stack) -------------------------
__global__ void ln_kernel(const float* __restrict__ x,
                          const float* __restrict__ w, int ws,
                          const float* __restrict__ b, int bs,
                          float* __restrict__ out) {
    int s = blockIdx.y;
    int row = blockIdx.x;
    int t = threadIdx.x;  // 128 threads, 4 floats each
    const float* xr = x + (size_t)s * T * D + row * D;
    const float* wp = w + (size_t)s * ws;
    const float* bp = b + (size_t)s * bs;
    float4 v = *(const float4*)(xr + t * 4);
    float sm_ = v.x + v.y + v.z + v.w;
    float ss = v.x * v.x + v.y * v.y + v.z * v.z + v.w * v.w;
    #pragma unroll
    for (int o = 16; o > 0; o >>= 1) {
        sm_ += __shfl_xor_sync(0xffffffffu, sm_, o);
        ss  += __shfl_xor_sync(0xffffffffu, ss, o);
    }
    __shared__ float sh[8];
    int wid = t >> 5, lane = t & 31;
    if (lane == 0) { sh[wid] = sm_; sh[4 + wid] = ss; }
    __syncthreads();
    float S  = sh[0] + sh[1] + sh[2] + sh[3];
    float SS = sh[4] + sh[5] + sh[6] + sh[7];
    float mu = S * (1.0f / D);
    float var = SS * (1.0f / D) - mu * mu;
    float rstd = rsqrtf(var + 1e-5f);
    float4 wv = *(const float4*)(wp + t * 4);
    float4 bv = *(const float4*)(bp + t * 4);
    float4 r;
    r.x = (v.x - mu) * rstd * wv.x + bv.x;
    r.y = (v.y - mu) * rstd * wv.y + bv.y;
    r.z = (v.z - mu) * rstd * wv.z + bv.z;
    r.w = (v.w - mu) * rstd * wv.w + bv.w;
    *(float4*)(out + (size_t)s * T * D + row * D + t * 4) = r;
}

// ---------------- TF32 tensor-core GEMM core ---------------------------------
#define BM 128
#define BN 64
#define BK 32
#define APAD 36
#define BPAD 68
#define NSTG 3
#define STAGE_F (BM * APAD + BK * BPAD)   // 6784 floats / stage
#define GEMM_SMEM (NSTG * STAGE_F * 4)    // 81408 bytes

__device__ __forceinline__ void gemm_body(
    const float* __restrict__ A, const float* __restrict__ W,
    const float* __restrict__ bias, const float* __restrict__ res,
    float* __restrict__ C, int N, int K, int act,
    int m0, int n0, float* sm)
{
    const int t = threadIdx.x;
    const int wid = t >> 5;
    const int wm0 = (wid & 1) * 64;
    const int wn0 = (wid >> 1) * 32;
    const unsigned smem_base = (unsigned)__cvta_generic_to_shared(sm);
    const int NITER = K / BK;

    auto load_stage = [&](int stg, int iter) {
        unsigned base = smem_base + stg * STAGE_F * 4;
        int k0 = iter * BK;
        #pragma unroll
        for (int i = 0; i < 8; i++) {        // A: 128x32, 8 chunks/row
            int c = t + i * 128;
            int rowa = c >> 3, cola = (c & 7) * 4;
            cp_async16(base + (rowa * APAD + cola) * 4,
                       A + (size_t)(m0 + rowa) * K + k0 + cola);
        }
        unsigned bbase = base + BM * APAD * 4;
        #pragma unroll
        for (int i = 0; i < 4; i++) {        // B: 32x64, 16 chunks/row
            int c = t + i * 128;
            int rowb = c >> 4, colb = (c & 15) * 4;
            cp_async16(bbase + (rowb * BPAD + colb) * 4,
                       W + (size_t)(k0 + rowb) * N + n0 + colb);
        }
    };

    wmma::fragment<wmma::accumulator, 16, 16, 8, float> acc[4][2];
    #pragma unroll
    for (int i = 0; i < 4; i++)
        #pragma unroll
        for (int j = 0; j < 2; j++)
            wmma::fill_fragment(acc[i][j], 0.0f);

    #pragma unroll
    for (int p = 0; p < NSTG - 1; p++) { load_stage(p, p); cp_commit(); }

    for (int it = 0; it < NITER; it++) {
        cp_wait<NSTG - 2>();
        __syncthreads();
        if (it + NSTG - 1 < NITER) load_stage((it + NSTG - 1) % NSTG, it + NSTG - 1);
        cp_commit();

        const float* As = sm + (it % NSTG) * STAGE_F;
        const float* Bs = As + BM * APAD;
        #pragma unroll
        for (int kk = 0; kk < BK; kk += 8) {
            wmma::fragment<wmma::matrix_a, 16, 16, 8, wmma::precision::tf32, wmma::row_major> af[4];
            wmma::fragment<wmma::matrix_b, 16, 16, 8, wmma::precision::tf32, wmma::row_major> bf[2];
            #pragma unroll
            for (int i = 0; i < 4; i++)
                wmma::load_matrix_sync(af[i], As + (wm0 + 16 * i) * APAD + kk, APAD);
            #pragma unroll
            for (int j = 0; j < 2; j++)
                wmma::load_matrix_sync(bf[j], Bs + kk * BPAD + wn0 + 16 * j, BPAD);
            #pragma unroll
            for (int i = 0; i < 4; i++)
                #pragma unroll
                for (int j = 0; j < 2; j++)
                    wmma::mma_sync(acc[i][j], af[i], bf[j], acc[i][j]);
        }
    }

    __syncthreads();
    #pragma unroll
    for (int i = 0; i < 4; i++)
        #pragma unroll
        for (int j = 0; j < 2; j++)
            wmma::store_matrix_sync(sm + (wm0 + 16 * i) * BPAD + wn0 + 16 * j,
                                    acc[i][j], BPAD, wmma::mem_row_major);
    __syncthreads();

    const int cr = t >> 4, cc = (t & 15) * 4;
    float4 bb = *(const float4*)(bias + n0 + cc);
    #pragma unroll
    for (int i = 0; i < 16; i++) {
        int r = cr + 8 * i;
        int m = m0 + r;
        float4 v = *(const float4*)(sm + r * BPAD + cc);
        v.x += bb.x; v.y += bb.y; v.z += bb.z; v.w += bb.w;
        if (act == 1) {
            v.x = 0.5f * v.x * (1.0f + erff(v.x * 0.70710678118654752f));
            v.y = 0.5f * v.y * (1.0f + erff(v.y * 0.70710678118654752f));
            v.z = 0.5f * v.z * (1.0f + erff(v.z * 0.70710678118654752f));
            v.w = 0.5f * v.w * (1.0f + erff(v.w * 0.70710678118654752f));
        }
        if (res) {
            float4 rv = *(const float4*)(res + (size_t)m * N + n0 + cc);
            v.x += rv.x; v.y += rv.y; v.z += rv.z; v.w += rv.w;
        }
        *(float4*)(C + (size_t)m * N + n0 + cc) = v;
    }
}

__global__ __launch_bounds__(128)
void gemm_tc_kernel(const float* __restrict__ A,  size_t aS,
                    const float* __restrict__ W,  size_t wS,
                    const float* __restrict__ bias, size_t biasS,
                    const float* __restrict__ res,  size_t resS,
                    float* __restrict__ C, size_t cS,
                    int N, int K, int act) {
    extern __shared__ float sm[];
    const int s = blockIdx.z;
    gemm_body(A + s * aS, W + s * wS, bias + s * biasS,
              res ? res + s * resS : nullptr, C + s * cS,
              N, K, act,
              blockIdx.y * BM, blockIdx.x * BN, sm);
}

__global__ __launch_bounds__(128)
void gemm_qkv_kernel(const float* __restrict__ A,  size_t aS,
                     const float* __restrict__ W0,
                     const float* __restrict__ W1_,
                     const float* __restrict__ W2_, size_t wS,
                     const float* __restrict__ b0,
                     const float* __restrict__ b1_,
                     const float* __restrict__ b2_, size_t biasS,
                     float* __restrict__ C0,
                     float* __restrict__ C1,
                     float* __restrict__ C2, size_t cS) {
    extern __shared__ float sm[];
    const int z = blockIdx.z;
    const int which = z >> 1, s = z & 1;
    const float* W = (which == 0) ? W0 : (which == 1) ? W1_ : W2_;
    const float* bia = (which == 0) ? b0 : (which == 1) ? b1_ : b2_;
    float* C = (which == 0) ? C0 : (which == 1) ? C1 : C2;
    gemm_body(A + s * aS, W + s * wS, bia + s * biasS, nullptr, C + s * cS,
              D, D, 0,
              blockIdx.y * BM, blockIdx.x * BN, sm);
}

// ---------------- PTX-mma flash attention (register softmax) -----------------
// grid (T/128, H, 2), 256 threads (8 warps). BQ=128, key tile 64, Dh=64.
// Warp owns 16 query rows. m16n8k8 tf32 mma; softmax + P + O all in registers.
// K pitch 68 / V pitch 72 chosen so operand LDS are bank-conflict-free.
#define KP 68
#define VP 72
#define AKF (64 * KP)
#define AVF (64 * VP)
#define ATTN_SMEM ((2 * AKF + 2 * AVF) * 4)   // 71680 bytes

__global__ __launch_bounds__(256)
void attn_tc_kernel(const float* __restrict__ qp,
                    const float* __restrict__ kp,
                    const float* __restrict__ vp,
                    float* __restrict__ out) {
    extern __shared__ float smdyn[];
    float* Kb = smdyn;             // [2][64][KP]
    float* Vb = smdyn + 2 * AKF;   // [2][64][VP]

    const int t = threadIdx.x;
    const int w = t >> 5;
    const int lane = t & 31;
    const int g = lane >> 2, qd = lane & 3;
    const int q0 = blockIdx.x * 128;
    const int head = blockIdx.y;
    const int stk = blockIdx.z;
    const int bw = stk == 0 ? 999 : 9;
    const size_t sb = (size_t)stk * T * D;
    const float* qh = qp + sb + head * DH;
    const float* kh = kp + sb + head * DH;
    const float* vh = vp + sb + head * DH;
    const unsigned kb_base = (unsigned)__cvta_generic_to_shared(Kb);
    const unsigned vb_base = (unsigned)__cvta_generic_to_shared(Vb);

    const int r1 = q0 + 16 * w + g;   // global query rows owned by this thread
    const int r2 = r1 + 8;

    // Q fragments (A-layout, pre-scaled), loaded once: aq[kc][0..3]
    unsigned aq[8][4];
    #pragma unroll
    for (int kc = 0; kc < 8; kc++) {
        aq[kc][0] = __float_as_uint(qh[(size_t)r1 * D + 8 * kc + qd] * 0.125f);
        aq[kc][1] = __float_as_uint(qh[(size_t)r2 * D + 8 * kc + qd] * 0.125f);
        aq[kc][2] = __float_as_uint(qh[(size_t)r1 * D + 8 * kc + qd + 4] * 0.125f);
        aq[kc][3] = __float_as_uint(qh[(size_t)r2 * D + 8 * kc + qd + 4] * 0.125f);
    }

    auto load_kv = [&](int buf, int j0) {
        unsigned kb = kb_base + buf * AKF * 4;
        unsigned vb = vb_base + buf * AVF * 4;
        #pragma unroll
        for (int i = 0; i < 4; i++) {
            int c = t + i * 256;
            int r = c >> 4, col = (c & 15) * 4;
            cp_async16(kb + (r * KP + col) * 4, kh + (size_t)(j0 + r) * D + col);
            cp_async16(vb + (r * VP + col) * 4, vh + (size_t)(j0 + r) * D + col);
        }
    };

    float o[8][4];
    #pragma unroll
    for (int nc = 0; nc < 8; nc++)
        #pragma unroll
        for (int e = 0; e < 4; e++) o[nc][e] = 0.f;
    float m1 = -1e30f, m2 = -1e30f, l1 = 0.f, l2 = 0.f;

    const int kt0 = max(0, q0 - bw) >> 6;
    const int kt1 = (q0 + 127) >> 6;

    load_kv(0, kt0 << 6); cp_commit();

    const int src1 = (lane & ~3) | (qd >> 1);
    const int src2 = src1 + 2;
    const bool oddq = qd & 1;

    for (int kt = kt0; kt <= kt1; kt++) {
        const int j0 = kt << 6;
        const int buf = (kt - kt0) & 1;
        if (kt < kt1) { load_kv(buf ^ 1, (kt + 1) << 6); cp_commit(); cp_wait<1>(); }
        else          { cp_wait<0>(); }
        __syncthreads();

        const float* Ks = Kb + buf * AKF;
        const float* Vs = Vb + buf * AVF;

        // S = Q @ K^T : sacc[nc] covers keys [8nc, 8nc+8)
        float sacc[8][4];
        #pragma unroll
        for (int nc = 0; nc < 8; nc++)
            #pragma unroll
            for (int e = 0; e < 4; e++) sacc[nc][e] = 0.f;
        #pragma unroll
        for (int kc = 0; kc < 8; kc++) {
            #pragma unroll
            for (int nc = 0; nc < 8; nc++) {
                unsigned b[2];
                b[0] = __float_as_uint(Ks[(8 * nc + g) * KP + 8 * kc + qd]);
                b[1] = __float_as_uint(Ks[(8 * nc + g) * KP + 8 * kc + qd + 4]);
                mma_tf32(sacc[nc], aq[kc], b);
            }
        }

        // band mask + online softmax on accumulator registers
        // c0/c1: row r1, cols j0+8nc+2qd(+1); c2/c3: row r2
        float mx1 = -1e30f, mx2 = -1e30f;
        #pragma unroll
        for (int nc = 0; nc < 8; nc++) {
            int kj = j0 + 8 * nc + 2 * qd;
            if (kj > r1 || kj < r1 - bw) sacc[nc][0] = -1e30f;
            if (kj + 1 > r1 || kj + 1 < r1 - bw) sacc[nc][1] = -1e30f;
            if (kj > r2 || kj < r2 - bw) sacc[nc][2] = -1e30f;
            if (kj + 1 > r2 || kj + 1 < r2 - bw) sacc[nc][3] = -1e30f;
            mx1 = fmaxf(mx1, fmaxf(sacc[nc][0], sacc[nc][1]));
            mx2 = fmaxf(mx2, fmaxf(sacc[nc][2], sacc[nc][3]));
        }
        mx1 = fmaxf(mx1, __shfl_xor_sync(0xffffffffu, mx1, 1));
        mx1 = fmaxf(mx1, __shfl_xor_sync(0xffffffffu, mx1, 2));
        mx2 = fmaxf(mx2, __shfl_xor_sync(0xffffffffu, mx2, 1));
        mx2 = fmaxf(mx2, __shfl_xor_sync(0xffffffffu, mx2, 2));
        float mn1 = fmaxf(m1, mx1), mn2 = fmaxf(m2, mx2);
        float al1 = __expf(m1 - mn1), al2 = __expf(m2 - mn2);
        float rs1 = 0.f, rs2 = 0.f;
        #pragma unroll
        for (int nc = 0; nc < 8; nc++) {
            float p0 = (sacc[nc][0] < -1e29f) ? 0.f : __expf(sacc[nc][0] - mn1);
            float p1 = (sacc[nc][1] < -1e29f) ? 0.f : __expf(sacc[nc][1] - mn1);
            float p2 = (sacc[nc][2] < -1e29f) ? 0.f : __expf(sacc[nc][2] - mn2);
            float p3 = (sacc[nc][3] < -1e29f) ? 0.f : __expf(sacc[nc][3] - mn2);
            sacc[nc][0] = p0; sacc[nc][1] = p1; sacc[nc][2] = p2; sacc[nc][3] = p3;
            rs1 += p0 + p1; rs2 += p2 + p3;
        }
        rs1 += __shfl_xor_sync(0xffffffffu, rs1, 1);
        rs1 += __shfl_xor_sync(0xffffffffu, rs1, 2);
        rs2 += __shfl_xor_sync(0xffffffffu, rs2, 1);
        rs2 += __shfl_xor_sync(0xffffffffu, rs2, 2);
        m1 = mn1; m2 = mn2;
        l1 = l1 * al1 + rs1; l2 = l2 * al2 + rs2;
        #pragma unroll
        for (int nc = 0; nc < 8; nc++) {
            o[nc][0] *= al1; o[nc][1] *= al1;
            o[nc][2] *= al2; o[nc][3] *= al2;
        }

        // convert P from C-layout to A-layout (per key-chunk), then O += P @ V
        #pragma unroll
        for (int kc = 0; kc < 8; kc++) {
            float s1c0 = __shfl_sync(0xffffffffu, sacc[kc][0], src1);
            float s1c1 = __shfl_sync(0xffffffffu, sacc[kc][1], src1);
            float s1c2 = __shfl_sync(0xffffffffu, sacc[kc][2], src1);
            float s1c3 = __shfl_sync(0xffffffffu, sacc[kc][3], src1);
            float s2c0 = __shfl_sync(0xffffffffu, sacc[kc][0], src2);
            float s2c1 = __shfl_sync(0xffffffffu, sacc[kc][1], src2);
            float s2c2 = __shfl_sync(0xffffffffu, sacc[kc][2], src2);
            float s2c3 = __shfl_sync(0xffffffffu, sacc[kc][3], src2);
            unsigned pa[4];
            pa[0] = __float_as_uint(oddq ? s1c1 : s1c0);
            pa[1] = __float_as_uint(oddq ? s1c3 : s1c2);
            pa[2] = __float_as_uint(oddq ? s2c1 : s2c0);
            pa[3] = __float_as_uint(oddq ? s2c3 : s2c2);
            #pragma unroll
            for (int nc = 0; nc < 8; nc++) {
                unsigned b[2];
                b[0] = __float_as_uint(Vs[(8 * kc + qd) * VP + 8 * nc + g]);
                b[1] = __float_as_uint(Vs[(8 * kc + qd + 4) * VP + 8 * nc + g]);
                mma_tf32(o[nc], pa, b);
            }
        }
        __syncthreads();   // all warps done with this K/V buffer before reuse
    }

    // normalize + write: c0,c1 -> (r1, 8nc+2qd); c2,c3 -> (r2, ...)
    const float inv1 = 1.0f / l1, inv2 = 1.0f / l2;
    float* o1 = out + sb + (size_t)r1 * D + head * DH;
    float* o2 = out + sb + (size_t)r2 * D + head * DH;
    #pragma unroll
    for (int nc = 0; nc < 8; nc++) {
        float2 u = {o[nc][0] * inv1, o[nc][1] * inv1};
        float2 v2 = {o[nc][2] * inv2, o[nc][3] * inv2};
        *(float2*)(o1 + 8 * nc + 2 * qd) = u;
        *(float2*)(o2 + 8 * nc + 2 * qd) = v2;
    }
}

// ---------------- host orchestration ----------------------------------------
extern "C" void kernel_launch(void* const* d_in, const int* in_sizes, int n_in,
                              void* d_out, int out_size) {
    const float* x      = (const float*)d_in[0];
    const float* pos    = (const float*)d_in[1];
    const float* ln1_w  = (const float*)d_in[2];
    const float* ln1_b  = (const float*)d_in[3];
    const float* ln2_w  = (const float*)d_in[4];
    const float* ln2_b  = (const float*)d_in[5];
    const float* Wq     = (const float*)d_in[6];
    const float* bq     = (const float*)d_in[7];
    const float* Wk     = (const float*)d_in[8];
    const float* bk     = (const float*)d_in[9];
    const float* Wv     = (const float*)d_in[10];
    const float* bv     = (const float*)d_in[11];
    const float* Wo     = (const float*)d_in[12];
    const float* bo     = (const float*)d_in[13];
    const float* W1     = (const float*)d_in[14];
    const float* b1     = (const float*)d_in[15];
    const float* W2     = (const float*)d_in[16];
    const float* b2     = (const float*)d_in[17];
    const float* lnf_w  = (const float*)d_in[18];
    const float* lnf_b  = (const float*)d_in[19];
    float* out = (float*)d_out;

    float *ph, *pln, *pq, *pk, *pv, *pa, *pf;
    cudaGetSymbolAddress((void**)&ph,  g_h);
    cudaGetSymbolAddress((void**)&pln, g_ln);
    cudaGetSymbolAddress((void**)&pq,  g_q);
    cudaGetSymbolAddress((void**)&pk,  g_k);
    cudaGetSymbolAddress((void**)&pv,  g_v);
    cudaGetSymbolAddress((void**)&pa,  g_att);
    cudaGetSymbolAddress((void**)&pf,  g_ff);

    cudaFuncSetAttribute(attn_tc_kernel,
                         cudaFuncAttributeMaxDynamicSharedMemorySize, ATTN_SMEM);
    cudaFuncSetAttribute(gemm_tc_kernel,
                         cudaFuncAttributeMaxDynamicSharedMemorySize, GEMM_SMEM);
    cudaFuncSetAttribute(gemm_qkv_kernel,
                         cudaFuncAttributeMaxDynamicSharedMemorySize, GEMM_SMEM);

    const size_t SD   = (size_t)T * D;
    const size_t SF   = (size_t)T * FF;
    const size_t WS   = (size_t)NL * D * D;
    const size_t W1S  = (size_t)NL * D * FF;
    const size_t BS   = (size_t)NL * D;
    const size_t B1S  = (size_t)NL * FF;

    add_pos_kernel<<<T * D / 4 / 256, 256>>>(x, pos, ph);

    for (int l = 0; l < NL; l++) {
        const size_t wo  = (size_t)l * D * D;
        const size_t w1o = (size_t)l * D * FF;
        const size_t w2o = (size_t)l * FF * D;
        const size_t bo_ = (size_t)l * D;
        const size_t b1o = (size_t)l * FF;

        ln_kernel<<<dim3(T, 2), 128>>>(ph, ln1_w + bo_, (int)BS, ln1_b + bo_, (int)BS, pln);

        gemm_qkv_kernel<<<dim3(D / BN, T / BM, 6), 128, GEMM_SMEM>>>(
            pln, SD, Wq + wo, Wk + wo, Wv + wo, WS,
            bq + bo_, bk + bo_, bv + bo_, BS, pq, pk, pv, SD);

        attn_tc_kernel<<<dim3(T / 128, H, 2), 256, ATTN_SMEM>>>(pq, pk, pv, pa);

        gemm_tc_kernel<<<dim3(D / BN, T / BM, 2), 128, GEMM_SMEM>>>(
            pa, SD, Wo + wo, WS, bo + bo_, BS, ph, SD, ph, SD, D, D, 0);

        ln_kernel<<<dim3(T, 2), 128>>>(ph, ln2_w + bo_, (int)BS, ln2_b + bo_, (int)BS, pln);

        gemm_tc_kernel<<<dim3(FF / BN, T / BM, 2), 128, GEMM_SMEM>>>(
            pln, SD, W1 + w1o, W1S, b1 + b1o, B1S, nullptr, 0, pf, SF, FF, D, 1);
        gemm_tc_kernel<<<dim3(D / BN, T / BM, 2), 128, GEMM_SMEM>>>(
            pf, SF, W2 + w2o, W1S, b2 + bo_, BS, ph, SD, ph, SD, D, FF, 0);
    }
    ln_kernel<<<dim3(T, 2), 128>>>(ph, lnf_w, 0, lnf_b, 0, out);
}

// round 17
// speedup vs baseline: 3.8749x; 1.6546x over previous
#include <cuda_runtime.h>
#include <cstdint>
#include <cstddef>
#include <math.h>

#define T 2048
#define D 512
#define H 8
#define DH 64
#define NL 2
#define FF 1024

// ---------------- scratch (per-stack: 2x) -----------------------------------
__device__ float g_h  [2 * T * D];
__device__ float g_ln [2 * T * D];
__device__ float g_q  [2 * T * D];
__device__ float g_k  [2 * T * D];
__device__ float g_v  [2 * T * D];
__device__ float g_att[2 * T * D];
__device__ float g_ff [2 * T * FF];

// ---------------- cp.async helpers -------------------------------------------
__device__ __forceinline__ void cp_async16(unsigned smem, const void* gmem) {
    asm volatile("cp.async.cg.shared.global [%0], [%1], 16;\n" :: "r"(smem), "l"(gmem));
}
__device__ __forceinline__ void cp_commit() {
    asm volatile("cp.async.commit_group;\n");
}
template<int N>
__device__ __forceinline__ void cp_wait() {
    asm volatile("cp.async.wait_group %0;\n" :: "n"(N));
}

// m16n8k8 tf32 mma, in-place accumulate
__device__ __forceinline__ void mma_tf32(float* d, const unsigned* a, const unsigned* b) {
    asm volatile(
        "mma.sync.aligned.m16n8k8.row.col.f32.tf32.tf32.f32 "
        "{%0,%1,%2,%3}, {%4,%5,%6,%7}, {%8,%9}, {%0,%1,%2,%3};\n"
        : "+f"(d[0]), "+f"(d[1]), "+f"(d[2]), "+f"(d[3])
        : "r"(a[0]), "r"(a[1]), "r"(a[2]), "r"(a[3]), "r"(b[0]), "r"(b[1]));
}

__device__ __forceinline__ float gelu1(float x) {
    return 0.5f * x * (1.0f + erff(x * 0.70710678118654752f));
}

// ---------------- x + pos -> both stacks -------------------------------------
__global__ void add_pos_kernel(const float* __restrict__ x,
                               const float* __restrict__ pos,
                               float* __restrict__ out) {
    int i = blockIdx.x * blockDim.x + threadIdx.x;   // float4 index
    float4 a = ((const float4*)x)[i];
    float4 b = ((const float4*)pos)[i];
    a.x += b.x; a.y += b.y; a.z += b.z; a.w += b.w;
    ((float4*)out)[i] = a;
    ((float4*)(out + T * D))[i] = a;
}

// ---------------- batched LayerNorm (grid.y = stack) -------------------------
__global__ void ln_kernel(const float* __restrict__ x,
                          const float* __restrict__ w, int ws,
                          const float* __restrict__ b, int bs,
                          float* __restrict__ out) {
    int s = blockIdx.y;
    int row = blockIdx.x;
    int t = threadIdx.x;  // 128 threads, 4 floats each
    const float* xr = x + (size_t)s * T * D + row * D;
    const float* wp = w + (size_t)s * ws;
    const float* bp = b + (size_t)s * bs;
    float4 v = *(const float4*)(xr + t * 4);
    float sm_ = v.x + v.y + v.z + v.w;
    float ss = v.x * v.x + v.y * v.y + v.z * v.z + v.w * v.w;
    #pragma unroll
    for (int o = 16; o > 0; o >>= 1) {
        sm_ += __shfl_xor_sync(0xffffffffu, sm_, o);
        ss  += __shfl_xor_sync(0xffffffffu, ss, o);
    }
    __shared__ float sh[8];
    int wid = t >> 5, lane = t & 31;
    if (lane == 0) { sh[wid] = sm_; sh[4 + wid] = ss; }
    __syncthreads();
    float S  = sh[0] + sh[1] + sh[2] + sh[3];
    float SS = sh[4] + sh[5] + sh[6] + sh[7];
    float mu = S * (1.0f / D);
    float var = SS * (1.0f / D) - mu * mu;
    float rstd = rsqrtf(var + 1e-5f);
    float4 wv = *(const float4*)(wp + t * 4);
    float4 bv = *(const float4*)(bp + t * 4);
    float4 r;
    r.x = (v.x - mu) * rstd * wv.x + bv.x;
    r.y = (v.y - mu) * rstd * wv.y + bv.y;
    r.z = (v.z - mu) * rstd * wv.z + bv.z;
    r.w = (v.w - mu) * rstd * wv.w + bv.w;
    *(float4*)(out + (size_t)s * T * D + row * D + t * 4) = r;
}

// ---------------- PTX-mma TF32 GEMM ------------------------------------------
// Block 128x64, BK=32, 128 threads (4 warps 2x2), warp tile 64x32.
// 3-stage cp.async. Fragments via conflict-free scalar LDS:
//   A pitch 36 -> bank (4g+qd)%32 distinct; B pitch 72 -> (8qd+g)%32 distinct.
// Epilogue fully in registers (bias/GELU/residual), no smem round-trip.
#define BM 128
#define BN 64
#define BK 32
#define APAD 36
#define BPAD 72
#define NSTG 3
#define STAGE_F (BM * APAD + BK * BPAD)   // 6912 floats / stage
#define GEMM_SMEM (NSTG * STAGE_F * 4)    // 82944 bytes

__device__ __forceinline__ void gemm_body(
    const float* __restrict__ A, const float* __restrict__ W,
    const float* __restrict__ bias, const float* __restrict__ res,
    float* __restrict__ C, int N, int K, int act,
    int m0, int n0, float* sm)
{
    const int t = threadIdx.x;
    const int wid = t >> 5;
    const int lane = t & 31;
    const int g = lane >> 2, qd = lane & 3;
    const int wm0 = (wid & 1) * 64;
    const int wn0 = (wid >> 1) * 32;
    const unsigned smem_base = (unsigned)__cvta_generic_to_shared(sm);
    const int NITER = K / BK;

    auto load_stage = [&](int stg, int iter) {
        unsigned base = smem_base + stg * STAGE_F * 4;
        int k0 = iter * BK;
        #pragma unroll
        for (int i = 0; i < 8; i++) {        // A: 128x32, 8 chunks/row
            int c = t + i * 128;
            int rowa = c >> 3, cola = (c & 7) * 4;
            cp_async16(base + (rowa * APAD + cola) * 4,
                       A + (size_t)(m0 + rowa) * K + k0 + cola);
        }
        unsigned bbase = base + BM * APAD * 4;
        #pragma unroll
        for (int i = 0; i < 4; i++) {        // B: 32x64, 16 chunks/row
            int c = t + i * 128;
            int rowb = c >> 4, colb = (c & 15) * 4;
            cp_async16(bbase + (rowb * BPAD + colb) * 4,
                       W + (size_t)(k0 + rowb) * N + n0 + colb);
        }
    };

    float acc[4][4][4];
    #pragma unroll
    for (int mf = 0; mf < 4; mf++)
        #pragma unroll
        for (int nf = 0; nf < 4; nf++)
            #pragma unroll
            for (int e = 0; e < 4; e++) acc[mf][nf][e] = 0.f;

    #pragma unroll
    for (int p = 0; p < NSTG - 1; p++) { load_stage(p, p); cp_commit(); }

    for (int it = 0; it < NITER; it++) {
        cp_wait<NSTG - 2>();
        __syncthreads();
        if (it + NSTG - 1 < NITER) load_stage((it + NSTG - 1) % NSTG, it + NSTG - 1);
        cp_commit();

        const float* As = sm + (it % NSTG) * STAGE_F;
        const float* Bs = As + BM * APAD;
        #pragma unroll
        for (int kk = 0; kk < BK; kk += 8) {
            unsigned a[4][4], b[4][2];
            #pragma unroll
            for (int mf = 0; mf < 4; mf++) {
                int r1 = wm0 + 16 * mf + g;
                a[mf][0] = __float_as_uint(As[r1 * APAD + kk + qd]);
                a[mf][1] = __float_as_uint(As[(r1 + 8) * APAD + kk + qd]);
                a[mf][2] = __float_as_uint(As[r1 * APAD + kk + qd + 4]);
                a[mf][3] = __float_as_uint(As[(r1 + 8) * APAD + kk + qd + 4]);
            }
            #pragma unroll
            for (int nf = 0; nf < 4; nf++) {
                int n = wn0 + 8 * nf + g;
                b[nf][0] = __float_as_uint(Bs[(kk + qd) * BPAD + n]);
                b[nf][1] = __float_as_uint(Bs[(kk + qd + 4) * BPAD + n]);
            }
            #pragma unroll
            for (int mf = 0; mf < 4; mf++)
                #pragma unroll
                for (int nf = 0; nf < 4; nf++)
                    mma_tf32(acc[mf][nf], a[mf], b[nf]);
        }
    }

    // register epilogue: c0,c1 -> (r1, n..n+1); c2,c3 -> (r2, n..n+1)
    #pragma unroll
    for (int mf = 0; mf < 4; mf++) {
        int r1 = m0 + wm0 + 16 * mf + g;
        int r2 = r1 + 8;
        #pragma unroll
        for (int nf = 0; nf < 4; nf++) {
            int n = n0 + wn0 + 8 * nf + 2 * qd;
            float2 bb = *(const float2*)(bias + n);
            float v0 = acc[mf][nf][0] + bb.x;
            float v1 = acc[mf][nf][1] + bb.y;
            float v2 = acc[mf][nf][2] + bb.x;
            float v3 = acc[mf][nf][3] + bb.y;
            if (act == 1) {
                v0 = gelu1(v0); v1 = gelu1(v1); v2 = gelu1(v2); v3 = gelu1(v3);
            }
            if (res) {
                float2 ra = *(const float2*)(res + (size_t)r1 * N + n);
                float2 rb = *(const float2*)(res + (size_t)r2 * N + n);
                v0 += ra.x; v1 += ra.y; v2 += rb.x; v3 += rb.y;
            }
            float2 u = {v0, v1}, w2 = {v2, v3};
            *(float2*)(C + (size_t)r1 * N + n) = u;
            *(float2*)(C + (size_t)r2 * N + n) = w2;
        }
    }
}

__global__ __launch_bounds__(128)
void gemm_tc_kernel(const float* __restrict__ A,  size_t aS,
                    const float* __restrict__ W,  size_t wS,
                    const float* __restrict__ bias, size_t biasS,
                    const float* __restrict__ res,  size_t resS,
                    float* __restrict__ C, size_t cS,
                    int N, int K, int act) {
    extern __shared__ float sm[];
    const int s = blockIdx.z;
    gemm_body(A + s * aS, W + s * wS, bias + s * biasS,
              res ? res + s * resS : nullptr, C + s * cS,
              N, K, act,
              blockIdx.y * BM, blockIdx.x * BN, sm);
}

__global__ __launch_bounds__(128)
void gemm_qkv_kernel(const float* __restrict__ A,  size_t aS,
                     const float* __restrict__ W0,
                     const float* __restrict__ W1_,
                     const float* __restrict__ W2_, size_t wS,
                     const float* __restrict__ b0,
                     const float* __restrict__ b1_,
                     const float* __restrict__ b2_, size_t biasS,
                     float* __restrict__ C0,
                     float* __restrict__ C1,
                     float* __restrict__ C2, size_t cS) {
    extern __shared__ float sm[];
    const int z = blockIdx.z;
    const int which = z >> 1, s = z & 1;
    const float* W = (which == 0) ? W0 : (which == 1) ? W1_ : W2_;
    const float* bia = (which == 0) ? b0 : (which == 1) ? b1_ : b2_;
    float* C = (which == 0) ? C0 : (which == 1) ? C1 : C2;
    gemm_body(A + s * aS, W + s * wS, bia + s * biasS, nullptr, C + s * cS,
              D, D, 0,
              blockIdx.y * BM, blockIdx.x * BN, sm);
}

// ---------------- PTX-mma flash attention (register softmax) -----------------
// grid (T/128, H, 2), 256 threads (8 warps). BQ=128, key tile 64, Dh=64.
#define KP 68
#define VP 72
#define AKF (64 * KP)
#define AVF (64 * VP)
#define ATTN_SMEM ((2 * AKF + 2 * AVF) * 4)   // 71680 bytes

__global__ __launch_bounds__(256)
void attn_tc_kernel(const float* __restrict__ qp,
                    const float* __restrict__ kp,
                    const float* __restrict__ vp,
                    float* __restrict__ out) {
    extern __shared__ float smdyn[];
    float* Kb = smdyn;             // [2][64][KP]
    float* Vb = smdyn + 2 * AKF;   // [2][64][VP]

    const int t = threadIdx.x;
    const int w = t >> 5;
    const int lane = t & 31;
    const int g = lane >> 2, qd = lane & 3;
    const int q0 = blockIdx.x * 128;
    const int head = blockIdx.y;
    const int stk = blockIdx.z;
    const int bw = stk == 0 ? 999 : 9;
    const size_t sb = (size_t)stk * T * D;
    const float* qh = qp + sb + head * DH;
    const float* kh = kp + sb + head * DH;
    const float* vh = vp + sb + head * DH;
    const unsigned kb_base = (unsigned)__cvta_generic_to_shared(Kb);
    const unsigned vb_base = (unsigned)__cvta_generic_to_shared(Vb);

    const int r1 = q0 + 16 * w + g;
    const int r2 = r1 + 8;

    unsigned aq[8][4];
    #pragma unroll
    for (int kc = 0; kc < 8; kc++) {
        aq[kc][0] = __float_as_uint(qh[(size_t)r1 * D + 8 * kc + qd] * 0.125f);
        aq[kc][1] = __float_as_uint(qh[(size_t)r2 * D + 8 * kc + qd] * 0.125f);
        aq[kc][2] = __float_as_uint(qh[(size_t)r1 * D + 8 * kc + qd + 4] * 0.125f);
        aq[kc][3] = __float_as_uint(qh[(size_t)r2 * D + 8 * kc + qd + 4] * 0.125f);
    }

    auto load_kv = [&](int buf, int j0) {
        unsigned kb = kb_base + buf * AKF * 4;
        unsigned vb = vb_base + buf * AVF * 4;
        #pragma unroll
        for (int i = 0; i < 4; i++) {
            int c = t + i * 256;
            int r = c >> 4, col = (c & 15) * 4;
            cp_async16(kb + (r * KP + col) * 4, kh + (size_t)(j0 + r) * D + col);
            cp_async16(vb + (r * VP + col) * 4, vh + (size_t)(j0 + r) * D + col);
        }
    };

    float o[8][4];
    #pragma unroll
    for (int nc = 0; nc < 8; nc++)
        #pragma unroll
        for (int e = 0; e < 4; e++) o[nc][e] = 0.f;
    float m1 = -1e30f, m2 = -1e30f, l1 = 0.f, l2 = 0.f;

    const int kt0 = max(0, q0 - bw) >> 6;
    const int kt1 = (q0 + 127) >> 6;

    load_kv(0, kt0 << 6); cp_commit();

    const int src1 = (lane & ~3) | (qd >> 1);
    const int src2 = src1 + 2;
    const bool oddq = qd & 1;

    for (int kt = kt0; kt <= kt1; kt++) {
        const int j0 = kt << 6;
        const int buf = (kt - kt0) & 1;
        if (kt < kt1) { load_kv(buf ^ 1, (kt + 1) << 6); cp_commit(); cp_wait<1>(); }
        else          { cp_wait<0>(); }
        __syncthreads();

        const float* Ks = Kb + buf * AKF;
        const float* Vs = Vb + buf * AVF;

        float sacc[8][4];
        #pragma unroll
        for (int nc = 0; nc < 8; nc++)
            #pragma unroll
            for (int e = 0; e < 4; e++) sacc[nc][e] = 0.f;
        #pragma unroll
        for (int kc = 0; kc < 8; kc++) {
            #pragma unroll
            for (int nc = 0; nc < 8; nc++) {
                unsigned b[2];
                b[0] = __float_as_uint(Ks[(8 * nc + g) * KP + 8 * kc + qd]);
                b[1] = __float_as_uint(Ks[(8 * nc + g) * KP + 8 * kc + qd + 4]);
                mma_tf32(sacc[nc], aq[kc], b);
            }
        }

        float mx1 = -1e30f, mx2 = -1e30f;
        #pragma unroll
        for (int nc = 0; nc < 8; nc++) {
            int kj = j0 + 8 * nc + 2 * qd;
            if (kj > r1 || kj < r1 - bw) sacc[nc][0] = -1e30f;
            if (kj + 1 > r1 || kj + 1 < r1 - bw) sacc[nc][1] = -1e30f;
            if (kj > r2 || kj < r2 - bw) sacc[nc][2] = -1e30f;
            if (kj + 1 > r2 || kj + 1 < r2 - bw) sacc[nc][3] = -1e30f;
            mx1 = fmaxf(mx1, fmaxf(sacc[nc][0], sacc[nc][1]));
            mx2 = fmaxf(mx2, fmaxf(sacc[nc][2], sacc[nc][3]));
        }
        mx1 = fmaxf(mx1, __shfl_xor_sync(0xffffffffu, mx1, 1));
        mx1 = fmaxf(mx1, __shfl_xor_sync(0xffffffffu, mx1, 2));
        mx2 = fmaxf(mx2, __shfl_xor_sync(0xffffffffu, mx2, 1));
        mx2 = fmaxf(mx2, __shfl_xor_sync(0xffffffffu, mx2, 2));
        float mn1 = fmaxf(m1, mx1), mn2 = fmaxf(m2, mx2);
        float al1 = __expf(m1 - mn1), al2 = __expf(m2 - mn2);
        float rs1 = 0.f, rs2 = 0.f;
        #pragma unroll
        for (int nc = 0; nc < 8; nc++) {
            float p0 = (sacc[nc][0] < -1e29f) ? 0.f : __expf(sacc[nc][0] - mn1);
            float p1 = (sacc[nc][1] < -1e29f) ? 0.f : __expf(sacc[nc][1] - mn1);
            float p2 = (sacc[nc][2] < -1e29f) ? 0.f : __expf(sacc[nc][2] - mn2);
            float p3 = (sacc[nc][3] < -1e29f) ? 0.f : __expf(sacc[nc][3] - mn2);
            sacc[nc][0] = p0; sacc[nc][1] = p1; sacc[nc][2] = p2; sacc[nc][3] = p3;
            rs1 += p0 + p1; rs2 += p2 + p3;
        }
        rs1 += __shfl_xor_sync(0xffffffffu, rs1, 1);
        rs1 += __shfl_xor_sync(0xffffffffu, rs1, 2);
        rs2 += __shfl_xor_sync(0xffffffffu, rs2, 1);
        rs2 += __shfl_xor_sync(0xffffffffu, rs2, 2);
        m1 = mn1; m2 = mn2;
        l1 = l1 * al1 + rs1; l2 = l2 * al2 + rs2;
        #pragma unroll
        for (int nc = 0; nc < 8; nc++) {
            o[nc][0] *= al1; o[nc][1] *= al1;
            o[nc][2] *= al2; o[nc][3] *= al2;
        }

        #pragma unroll
        for (int kc = 0; kc < 8; kc++) {
            float s1c0 = __shfl_sync(0xffffffffu, sacc[kc][0], src1);
            float s1c1 = __shfl_sync(0xffffffffu, sacc[kc][1], src1);
            float s1c2 = __shfl_sync(0xffffffffu, sacc[kc][2], src1);
            float s1c3 = __shfl_sync(0xffffffffu, sacc[kc][3], src1);
            float s2c0 = __shfl_sync(0xffffffffu, sacc[kc][0], src2);
            float s2c1 = __shfl_sync(0xffffffffu, sacc[kc][1], src2);
            float s2c2 = __shfl_sync(0xffffffffu, sacc[kc][2], src2);
            float s2c3 = __shfl_sync(0xffffffffu, sacc[kc][3], src2);
            unsigned pa[4];
            pa[0] = __float_as_uint(oddq ? s1c1 : s1c0);
            pa[1] = __float_as_uint(oddq ? s1c3 : s1c2);
            pa[2] = __float_as_uint(oddq ? s2c1 : s2c0);
            pa[3] = __float_as_uint(oddq ? s2c3 : s2c2);
            #pragma unroll
            for (int nc = 0; nc < 8; nc++) {
                unsigned b[2];
                b[0] = __float_as_uint(Vs[(8 * kc + qd) * VP + 8 * nc + g]);
                b[1] = __float_as_uint(Vs[(8 * kc + qd + 4) * VP + 8 * nc + g]);
                mma_tf32(o[nc], pa, b);
            }
        }
        __syncthreads();
    }

    const float inv1 = 1.0f / l1, inv2 = 1.0f / l2;
    float* o1 = out + sb + (size_t)r1 * D + head * DH;
    float* o2 = out + sb + (size_t)r2 * D + head * DH;
    #pragma unroll
    for (int nc = 0; nc < 8; nc++) {
        float2 u = {o[nc][0] * inv1, o[nc][1] * inv1};
        float2 v2 = {o[nc][2] * inv2, o[nc][3] * inv2};
        *(float2*)(o1 + 8 * nc + 2 * qd) = u;
        *(float2*)(o2 + 8 * nc + 2 * qd) = v2;
    }
}

// ---------------- host orchestration ----------------------------------------
extern "C" void kernel_launch(void* const* d_in, const int* in_sizes, int n_in,
                              void* d_out, int out_size) {
    const float* x      = (const float*)d_in[0];
    const float* pos    = (const float*)d_in[1];
    const float* ln1_w  = (const float*)d_in[2];
    const float* ln1_b  = (const float*)d_in[3];
    const float* ln2_w  = (const float*)d_in[4];
    const float* ln2_b  = (const float*)d_in[5];
    const float* Wq     = (const float*)d_in[6];
    const float* bq     = (const float*)d_in[7];
    const float* Wk     = (const float*)d_in[8];
    const float* bk     = (const float*)d_in[9];
    const float* Wv     = (const float*)d_in[10];
    const float* bv     = (const float*)d_in[11];
    const float* Wo     = (const float*)d_in[12];
    const float* bo     = (const float*)d_in[13];
    const float* W1     = (const float*)d_in[14];
    const float* b1     = (const float*)d_in[15];
    const float* W2     = (const float*)d_in[16];
    const float* b2     = (const float*)d_in[17];
    const float* lnf_w  = (const float*)d_in[18];
    const float* lnf_b  = (const float*)d_in[19];
    float* out = (float*)d_out;

    float *ph, *pln, *pq, *pk, *pv, *pa, *pf;
    cudaGetSymbolAddress((void**)&ph,  g_h);
    cudaGetSymbolAddress((void**)&pln, g_ln);
    cudaGetSymbolAddress((void**)&pq,  g_q);
    cudaGetSymbolAddress((void**)&pk,  g_k);
    cudaGetSymbolAddress((void**)&pv,  g_v);
    cudaGetSymbolAddress((void**)&pa,  g_att);
    cudaGetSymbolAddress((void**)&pf,  g_ff);

    cudaFuncSetAttribute(attn_tc_kernel,
                         cudaFuncAttributeMaxDynamicSharedMemorySize, ATTN_SMEM);
    cudaFuncSetAttribute(gemm_tc_kernel,
                         cudaFuncAttributeMaxDynamicSharedMemorySize, GEMM_SMEM);
    cudaFuncSetAttribute(gemm_qkv_kernel,
                         cudaFuncAttributeMaxDynamicSharedMemorySize, GEMM_SMEM);

    const size_t SD   = (size_t)T * D;
    const size_t SF   = (size_t)T * FF;
    const size_t WS   = (size_t)NL * D * D;
    const size_t W1S  = (size_t)NL * D * FF;
    const size_t BS   = (size_t)NL * D;
    const size_t B1S  = (size_t)NL * FF;

    add_pos_kernel<<<T * D / 4 / 256, 256>>>(x, pos, ph);

    for (int l = 0; l < NL; l++) {
        const size_t wo  = (size_t)l * D * D;
        const size_t w1o = (size_t)l * D * FF;
        const size_t w2o = (size_t)l * FF * D;
        const size_t bo_ = (size_t)l * D;
        const size_t b1o = (size_t)l * FF;

        ln_kernel<<<dim3(T, 2), 128>>>(ph, ln1_w + bo_, (int)BS, ln1_b + bo_, (int)BS, pln);

        gemm_qkv_kernel<<<dim3(D / BN, T / BM, 6), 128, GEMM_SMEM>>>(
            pln, SD, Wq + wo, Wk + wo, Wv + wo, WS,
            bq + bo_, bk + bo_, bv + bo_, BS, pq, pk, pv, SD);

        attn_tc_kernel<<<dim3(T / 128, H, 2), 256, ATTN_SMEM>>>(pq, pk, pv, pa);

        gemm_tc_kernel<<<dim3(D / BN, T / BM, 2), 128, GEMM_SMEM>>>(
            pa, SD, Wo + wo, WS, bo + bo_, BS, ph, SD, ph, SD, D, D, 0);

        ln_kernel<<<dim3(T, 2), 128>>>(ph, ln2_w + bo_, (int)BS, ln2_b + bo_, (int)BS, pln);

        gemm_tc_kernel<<<dim3(FF / BN, T / BM, 2), 128, GEMM_SMEM>>>(
            pln, SD, W1 + w1o, W1S, b1 + b1o, B1S, nullptr, 0, pf, SF, FF, D, 1);
        gemm_tc_kernel<<<dim3(D / BN, T / BM, 2), 128, GEMM_SMEM>>>(
            pf, SF, W2 + w2o, W1S, b2 + bo_, BS, ph, SD, ph, SD, D, FF, 0);
    }
    ln_kernel<<<dim3(T, 2), 128>>>(ph, lnf_w, 0, lnf_b, 0, out);
}